// round 1
// baseline (speedup 1.0000x reference)
#include <cuda_runtime.h>
#include <math.h>

// ---------------- problem dims (fixed) ----------------
#define HID   512
#define EXPD  2048
#define BATCH 4
#define SEQ   4096
#define M_TOT (BATCH*SEQ)      // 16384

// scan chunking: 64 chunks of 64 steps = 4096
#define NCH 64
#define CHL 64

// ---------------- scratch (device globals; no allocation allowed) ----------------
__device__ float g_xin  [(size_t)M_TOT*EXPD];   // silu(x@W_in1+b1)
__device__ float g_xskip[(size_t)M_TOT*EXPD];   // silu(x@W_in2+b2); later x_skip + h
__device__ float g_z    [(size_t)M_TOT*EXPD];   // sigmoid(x_in@Wz+bz)
__device__ float g_ht   [(size_t)M_TOT*EXPD];   // x_in@Wh+bh
__device__ float g_aggA [(size_t)BATCH*NCH*EXPD];
__device__ float g_aggB [(size_t)BATCH*NCH*EXPD];
__device__ float g_carry[(size_t)BATCH*NCH*EXPD];

// ---------------- tiled fp32 GEMM with fused bias + activation ----------------
// C[M,N] = act(A[M,K] @ W[K,N] + bias[N])
// ACT: 0 = none, 1 = silu, 2 = sigmoid
#define BM 128
#define BN 128
#define BK 8
#define TM 8
#define TN 8

template<int ACT>
__global__ __launch_bounds__(256)
void gemm_act(const float* __restrict__ A, const float* __restrict__ W,
              const float* __restrict__ bias, float* __restrict__ C,
              int M, int N, int K)
{
    __shared__ float As[BK][BM];
    __shared__ float Bs[BK][BN];

    const int bm  = blockIdx.y * BM;
    const int bn  = blockIdx.x * BN;
    const int tid = threadIdx.x;

    // A tile load map: 128 rows x 8 k  -> 256 float4, one per thread
    const int a_row = tid >> 1;
    const int a_k4  = (tid & 1) * 4;
    // W tile load map: 8 rows x 128 cols -> 256 float4, one per thread
    const int b_row = tid >> 5;
    const int b_col = (tid & 31) * 4;

    const int tx = tid & 15;
    const int ty = tid >> 4;

    float acc[TM][TN];
    #pragma unroll
    for (int i = 0; i < TM; i++)
        #pragma unroll
        for (int j = 0; j < TN; j++)
            acc[i][j] = 0.f;

    for (int k0 = 0; k0 < K; k0 += BK) {
        float4 av = *(const float4*)&A[(size_t)(bm + a_row) * K + k0 + a_k4];
        As[a_k4 + 0][a_row] = av.x;
        As[a_k4 + 1][a_row] = av.y;
        As[a_k4 + 2][a_row] = av.z;
        As[a_k4 + 3][a_row] = av.w;
        *(float4*)&Bs[b_row][b_col] =
            *(const float4*)&W[(size_t)(k0 + b_row) * N + bn + b_col];
        __syncthreads();

        #pragma unroll
        for (int kk = 0; kk < BK; kk++) {
            float ar[TM], br[TN];
            #pragma unroll
            for (int i = 0; i < TM; i++) ar[i] = As[kk][ty * TM + i];
            #pragma unroll
            for (int j = 0; j < TN; j++) br[j] = Bs[kk][tx * TN + j];
            #pragma unroll
            for (int i = 0; i < TM; i++)
                #pragma unroll
                for (int j = 0; j < TN; j++)
                    acc[i][j] += ar[i] * br[j];
        }
        __syncthreads();
    }

    #pragma unroll
    for (int i = 0; i < TM; i++) {
        const int m = bm + ty * TM + i;
        #pragma unroll
        for (int j = 0; j < TN; j++) {
            const int n = bn + tx * TN + j;
            float v = acc[i][j] + bias[n];
            float r;
            if (ACT == 0) {
                r = v;
            } else if (ACT == 1) {            // silu
                float s = 1.f / (1.f + expf(-v));
                r = v * s;
            } else {                          // sigmoid
                r = 1.f / (1.f + expf(-v));
            }
            C[(size_t)m * N + n] = r;
        }
    }
}

// ---------------- scan pass 1: per-chunk (A,B) aggregates ----------------
// thread t -> f = t % EXPD, c = (t/EXPD) % NCH, bb = t/(EXPD*NCH)
// a_t = 1 - z_t ; b_t = z_t * ht_t computed on the fly.
__global__ __launch_bounds__(256)
void scan_pass1(const float* __restrict__ z, const float* __restrict__ ht,
                float* __restrict__ aggA, float* __restrict__ aggB)
{
    int t = blockIdx.x * blockDim.x + threadIdx.x;
    int f  = t % EXPD;
    int rc = t / EXPD;
    int c  = rc % NCH;
    int bb = rc / NCH;
    size_t base = ((size_t)bb * SEQ + (size_t)c * CHL) * EXPD + f;

    float A = 1.f, B = 0.f;
    #pragma unroll 4
    for (int i = 0; i < CHL; i++) {
        size_t idx = base + (size_t)i * EXPD;
        float zi = z[idx];
        float hi = ht[idx];
        float ai = 1.f - zi;
        float bi = zi * hi;
        A = A * ai;
        B = B * ai + bi;
    }
    aggA[t] = A;
    aggB[t] = B;
}

// ---------------- scan pass 2: prefix over chunk aggregates per chain ----------------
// one thread per (bb, f): carry[c] = h entering chunk c (h_0 = 0)
__global__ __launch_bounds__(256)
void scan_pass2(const float* __restrict__ aggA, const float* __restrict__ aggB,
                float* __restrict__ carry)
{
    int t = blockIdx.x * blockDim.x + threadIdx.x;   // 0 .. BATCH*EXPD-1
    int f  = t % EXPD;
    int bb = t / EXPD;
    size_t base = (size_t)bb * NCH * EXPD + f;

    float h = 0.f;
    for (int c = 0; c < NCH; c++) {
        size_t idx = base + (size_t)c * EXPD;
        carry[idx] = h;
        h = aggA[idx] * h + aggB[idx];
    }
}

// ---------------- scan pass 3: replay with carry, fuse x_skip + h in place ----------------
__global__ __launch_bounds__(256)
void scan_pass3(const float* __restrict__ z, const float* __restrict__ ht,
                const float* __restrict__ carry, float* __restrict__ xskip)
{
    int t = blockIdx.x * blockDim.x + threadIdx.x;
    int f  = t % EXPD;
    int rc = t / EXPD;
    int c  = rc % NCH;
    int bb = rc / NCH;
    size_t base = ((size_t)bb * SEQ + (size_t)c * CHL) * EXPD + f;

    float h = carry[t];
    #pragma unroll 4
    for (int i = 0; i < CHL; i++) {
        size_t idx = base + (size_t)i * EXPD;
        float zi = z[idx];
        float hi = ht[idx];
        float ai = 1.f - zi;
        float bi = zi * hi;
        h = ai * h + bi;
        xskip[idx] += h;        // becomes (x_skip + h)
    }
}

// ---------------- launch ----------------
extern "C" void kernel_launch(void* const* d_in, const int* in_sizes, int n_in,
                              void* d_out, int out_size)
{
    const float* x     = (const float*)d_in[0];
    const float* W_in1 = (const float*)d_in[1];
    const float* b_in1 = (const float*)d_in[2];
    const float* W_in2 = (const float*)d_in[3];
    const float* b_in2 = (const float*)d_in[4];
    const float* W_z   = (const float*)d_in[5];
    const float* b_z   = (const float*)d_in[6];
    const float* W_h   = (const float*)d_in[7];
    const float* b_h   = (const float*)d_in[8];
    const float* W_out = (const float*)d_in[9];
    const float* b_out = (const float*)d_in[10];
    float* out = (float*)d_out;

    float *p_xin, *p_xskip, *p_z, *p_ht, *p_aggA, *p_aggB, *p_carry;
    cudaGetSymbolAddress((void**)&p_xin,   g_xin);
    cudaGetSymbolAddress((void**)&p_xskip, g_xskip);
    cudaGetSymbolAddress((void**)&p_z,     g_z);
    cudaGetSymbolAddress((void**)&p_ht,    g_ht);
    cudaGetSymbolAddress((void**)&p_aggA,  g_aggA);
    cudaGetSymbolAddress((void**)&p_aggB,  g_aggB);
    cudaGetSymbolAddress((void**)&p_carry, g_carry);

    dim3 blk(256);

    // x_in = silu(x @ W_in1 + b1), x_skip = silu(x @ W_in2 + b2)
    dim3 g_in(EXPD / BN, M_TOT / BM);
    gemm_act<1><<<g_in, blk>>>(x, W_in1, b_in1, p_xin,   M_TOT, EXPD, HID);
    gemm_act<1><<<g_in, blk>>>(x, W_in2, b_in2, p_xskip, M_TOT, EXPD, HID);

    // z = sigmoid(x_in @ W_z + bz), ht = x_in @ W_h + bh
    dim3 g_gate(EXPD / BN, M_TOT / BM);
    gemm_act<2><<<g_gate, blk>>>(p_xin, W_z, b_z, p_z,  M_TOT, EXPD, EXPD);
    gemm_act<0><<<g_gate, blk>>>(p_xin, W_h, b_h, p_ht, M_TOT, EXPD, EXPD);

    // minGRU scan: h_t = (1-z_t) h_{t-1} + z_t ht_t  ; fuse x_skip += h
    int p1_threads = BATCH * NCH * EXPD;           // 524288
    scan_pass1<<<p1_threads / 256, blk>>>(p_z, p_ht, p_aggA, p_aggB);
    int p2_threads = BATCH * EXPD;                 // 8192
    scan_pass2<<<p2_threads / 256, blk>>>(p_aggA, p_aggB, p_carry);
    scan_pass3<<<p1_threads / 256, blk>>>(p_z, p_ht, p_carry, p_xskip);

    // out = (x_skip + h) @ W_out + b_out
    dim3 g_out(HID / BN, M_TOT / BM);
    gemm_act<0><<<g_out, blk>>>(p_xskip, W_out, b_out, out, M_TOT, HID, EXPD);
}

// round 5
// speedup vs baseline: 2.6092x; 2.6092x over previous
#include <cuda_runtime.h>
#include <cuda_bf16.h>
#include <cstdint>
#include <math.h>

// ---------------- problem dims (fixed) ----------------
#define HID   512
#define EXPD  2048
#define BATCH 4
#define SEQ   4096
#define M_TOT (BATCH*SEQ)      // 16384
#define NCH 64
#define CHL 64

// ---------------- scratch (device globals; 16B aligned for vector/cp.async access) -------
__device__ __align__(16) __nv_bfloat16 g_xhi [(size_t)M_TOT*HID];
__device__ __align__(16) __nv_bfloat16 g_xlo [(size_t)M_TOT*HID];
__device__ __align__(16) __nv_bfloat16 g_w1hi[(size_t)EXPD*HID];
__device__ __align__(16) __nv_bfloat16 g_w1lo[(size_t)EXPD*HID];
__device__ __align__(16) __nv_bfloat16 g_w2hi[(size_t)EXPD*HID];
__device__ __align__(16) __nv_bfloat16 g_w2lo[(size_t)EXPD*HID];
__device__ __align__(16) __nv_bfloat16 g_wzhi[(size_t)EXPD*EXPD];
__device__ __align__(16) __nv_bfloat16 g_wzlo[(size_t)EXPD*EXPD];
__device__ __align__(16) __nv_bfloat16 g_whhi[(size_t)EXPD*EXPD];
__device__ __align__(16) __nv_bfloat16 g_whlo[(size_t)EXPD*EXPD];
__device__ __align__(16) __nv_bfloat16 g_wohi[(size_t)HID*EXPD];
__device__ __align__(16) __nv_bfloat16 g_wolo[(size_t)HID*EXPD];
__device__ __align__(16) __nv_bfloat16 g_xinhi[(size_t)M_TOT*EXPD];
__device__ __align__(16) __nv_bfloat16 g_xinlo[(size_t)M_TOT*EXPD];
__device__ __align__(16) float g_z    [(size_t)M_TOT*EXPD];
__device__ __align__(16) float g_ht   [(size_t)M_TOT*EXPD];
__device__ __align__(16) float g_xskip[(size_t)M_TOT*EXPD];
__device__ __align__(16) __nv_bfloat16 g_uhi[(size_t)M_TOT*EXPD];
__device__ __align__(16) __nv_bfloat16 g_ulo[(size_t)M_TOT*EXPD];
__device__ __align__(16) float g_aggA [(size_t)BATCH*NCH*EXPD];
__device__ __align__(16) float g_aggB [(size_t)BATCH*NCH*EXPD];
__device__ __align__(16) float g_carry[(size_t)BATCH*NCH*EXPD];

// ---------------- PTX helpers (sm_80-era base features only) ----------------
__device__ __forceinline__ uint32_t smem_u32(const void* p) {
    uint32_t a;
    asm("{ .reg .u64 t; cvta.to.shared.u64 t, %1; cvt.u32.u64 %0, t; }" : "=r"(a) : "l"(p));
    return a;
}
__device__ __forceinline__ void cp16(uint32_t dst, const void* src) {
    asm volatile("cp.async.cg.shared.global [%0], [%1], 16;" :: "r"(dst), "l"(src));
}
#define CP_COMMIT() asm volatile("cp.async.commit_group;" ::: "memory")
#define CP_WAIT(n)  asm volatile("cp.async.wait_group %0;" :: "n"(n) : "memory")

__device__ __forceinline__ void ldsm4(uint32_t* r, uint32_t addr) {
    asm volatile("ldmatrix.sync.aligned.m8n8.x4.shared.b16 {%0,%1,%2,%3}, [%4];"
        : "=r"(r[0]), "=r"(r[1]), "=r"(r[2]), "=r"(r[3]) : "r"(addr));
}
__device__ __forceinline__ void mma_bf16(float* c, const uint32_t* a, const uint32_t* b) {
    asm volatile(
        "mma.sync.aligned.m16n8k16.row.col.f32.bf16.bf16.f32 "
        "{%0,%1,%2,%3}, {%4,%5,%6,%7}, {%8,%9}, {%0,%1,%2,%3};"
        : "+f"(c[0]), "+f"(c[1]), "+f"(c[2]), "+f"(c[3])
        : "r"(a[0]), "r"(a[1]), "r"(a[2]), "r"(a[3]), "r"(b[0]), "r"(b[1]));
}

// ---------------- mma.sync GEMM: C[M,N] = act(Ahi/lo[M,K] @ (Bhi/lo[N,K])^T + bias) ------
// split product: hi*hi + hi*lo + lo*hi
#define BM 128
#define BN 128
#define BK 64
// per-stage smem offsets (each tile: 128 rows x 64 bf16 = 16KB, SW128 swizzled)
#define T_AHI 0
#define T_ALO 16384
#define T_BHI 32768
#define T_BLO 49152
#define STAGE_BYTES 65536
#define SMEM_BYTES (2*STAGE_BYTES)

// ACT: 0=none 1=silu 2=sigmoid ; SPLIT_OUT: 0 -> Cf fp32 ; 1 -> Chi/Clo bf16
template<int ACT, int SPLIT_OUT>
__global__ __launch_bounds__(256)
void gemm_mma(const __nv_bfloat16* __restrict__ Ahi, const __nv_bfloat16* __restrict__ Alo,
              const __nv_bfloat16* __restrict__ Bhi, const __nv_bfloat16* __restrict__ Blo,
              const float* __restrict__ bias,
              float* __restrict__ Cf, __nv_bfloat16* __restrict__ Chi, __nv_bfloat16* __restrict__ Clo,
              int M, int N, int K)
{
    extern __shared__ char smem[];
    const uint32_t sb = smem_u32(smem);
    const int tid  = threadIdx.x;
    const int wid  = tid >> 5;
    const int lane = tid & 31;
    const int wm = wid >> 2;           // 0..1  -> m offset wm*64
    const int wn = wid & 3;            // 0..3  -> n offset wn*32
    const int bm = blockIdx.y * BM;
    const int bn = blockIdx.x * BN;

    const int Kv = K >> 3;             // row pitch in uint4 (8 bf16)
    const uint4* gA[2] = { (const uint4*)Ahi, (const uint4*)Alo };
    const uint4* gB[2] = { (const uint4*)Bhi, (const uint4*)Blo };

    const int nk = K / BK;

    // per-thread load map: 512 chunks (16B) per tile, 256 threads -> 2 per tile per pass
    // chunk index i: row = i>>3 (0..127 over 2 passes? No: 128 rows x 8 chunks = 1024)
    // 1024 chunks per tile / 256 threads = 4 iterations per tile.
    auto load_stage = [&](int buf, int kc) {
        const int kv0 = kc * (BK / 8);
        const uint32_t base = sb + buf * STAGE_BYTES;
        #pragma unroll
        for (int t = 0; t < 4; t++) {
            int i = tid + t * 256;
            int row = i >> 3, ch = i & 7;
            uint32_t so = (uint32_t)(row * 128 + ((ch ^ (row & 7)) << 4));
            size_t ga = (size_t)(bm + row) * Kv + kv0 + ch;
            size_t gb = (size_t)(bn + row) * Kv + kv0 + ch;
            cp16(base + T_AHI + so, gA[0] + ga);
            cp16(base + T_ALO + so, gA[1] + ga);
            cp16(base + T_BHI + so, gB[0] + gb);
            cp16(base + T_BLO + so, gB[1] + gb);
        }
    };

    float acc[4][4][4];
    #pragma unroll
    for (int mi = 0; mi < 4; mi++)
        #pragma unroll
        for (int ni = 0; ni < 4; ni++)
            #pragma unroll
            for (int q = 0; q < 4; q++)
                acc[mi][ni][q] = 0.f;

    load_stage(0, 0);
    CP_COMMIT();

    for (int kc = 0; kc < nk; kc++) {
        const int buf = kc & 1;
        if (kc + 1 < nk) {
            load_stage(buf ^ 1, kc + 1);
            CP_COMMIT();
            CP_WAIT(1);
        } else {
            CP_WAIT(0);
        }
        __syncthreads();

        const uint32_t st = sb + buf * STAGE_BYTES;
        #pragma unroll
        for (int kk = 0; kk < BK / 16; kk++) {
            const int byteCol = kk * 32 + ((lane >> 4) << 4);
            // B fragments: two x4 loads cover n0..15 and n16..31 (4 n8 tiles)
            uint32_t bh[4][2], bl[4][2];
            #pragma unroll
            for (int nt = 0; nt < 2; nt++) {
                int row = wn * 32 + nt * 16 + (lane & 15);
                uint32_t so = (uint32_t)(row * 128 + byteCol) ^ ((uint32_t)(row & 7) << 4);
                uint32_t r[4];
                ldsm4(r, st + T_BHI + so);
                bh[2*nt][0] = r[0]; bh[2*nt+1][0] = r[1];
                bh[2*nt][1] = r[2]; bh[2*nt+1][1] = r[3];
                ldsm4(r, st + T_BLO + so);
                bl[2*nt][0] = r[0]; bl[2*nt+1][0] = r[1];
                bl[2*nt][1] = r[2]; bl[2*nt+1][1] = r[3];
            }
            #pragma unroll
            for (int mi = 0; mi < 4; mi++) {
                int row = wm * 64 + mi * 16 + (lane & 15);
                uint32_t so = (uint32_t)(row * 128 + byteCol) ^ ((uint32_t)(row & 7) << 4);
                uint32_t ah[4], al[4];
                ldsm4(ah, st + T_AHI + so);
                ldsm4(al, st + T_ALO + so);
                #pragma unroll
                for (int ni = 0; ni < 4; ni++) {
                    mma_bf16(acc[mi][ni], ah, bh[ni]);
                    mma_bf16(acc[mi][ni], ah, bl[ni]);
                    mma_bf16(acc[mi][ni], al, bh[ni]);
                }
            }
        }
        __syncthreads();
    }

    // ---------------- epilogue: bias + activation + store ----------------
    const int qrow = lane >> 2;        // 0..7
    const int qcol = (lane & 3) * 2;   // 0,2,4,6
    #pragma unroll
    for (int mi = 0; mi < 4; mi++) {
        #pragma unroll
        for (int ni = 0; ni < 4; ni++) {
            const int n0 = bn + wn * 32 + ni * 8 + qcol;
            const float bias0 = bias[n0], bias1 = bias[n0 + 1];
            #pragma unroll
            for (int half = 0; half < 2; half++) {
                const int m = bm + wm * 64 + mi * 16 + qrow + half * 8;
                float v0 = acc[mi][ni][half * 2 + 0] + bias0;
                float v1 = acc[mi][ni][half * 2 + 1] + bias1;
                if (ACT == 1) {
                    v0 *= 1.f / (1.f + expf(-v0));
                    v1 *= 1.f / (1.f + expf(-v1));
                } else if (ACT == 2) {
                    v0 = 1.f / (1.f + expf(-v0));
                    v1 = 1.f / (1.f + expf(-v1));
                }
                if (SPLIT_OUT) {
                    __nv_bfloat16 h0 = __float2bfloat16(v0);
                    __nv_bfloat16 h1 = __float2bfloat16(v1);
                    __nv_bfloat16 l0 = __float2bfloat16(v0 - __bfloat162float(h0));
                    __nv_bfloat16 l1 = __float2bfloat16(v1 - __bfloat162float(h1));
                    uint32_t hp = (uint32_t)__bfloat16_as_ushort(h0) | ((uint32_t)__bfloat16_as_ushort(h1) << 16);
                    uint32_t lp = (uint32_t)__bfloat16_as_ushort(l0) | ((uint32_t)__bfloat16_as_ushort(l1) << 16);
                    *(uint32_t*)&Chi[(size_t)m * N + n0] = hp;
                    *(uint32_t*)&Clo[(size_t)m * N + n0] = lp;
                } else {
                    *(float2*)&Cf[(size_t)m * N + n0] = make_float2(v0, v1);
                }
            }
        }
    }
}

// ---------------- weight transpose + split: W[K,N] fp32 -> T[N,K] bf16 hi/lo -------------
__global__ __launch_bounds__(256)
void transpose_split(const float* __restrict__ W, __nv_bfloat16* __restrict__ Thi,
                     __nv_bfloat16* __restrict__ Tlo, int K, int N)
{
    __shared__ float t[32][33];
    const int n0 = blockIdx.x * 32, k0 = blockIdx.y * 32;
    const int tx = threadIdx.x & 31, ty0 = threadIdx.x >> 5;
    #pragma unroll
    for (int dy = 0; dy < 32; dy += 8)
        t[ty0 + dy][tx] = W[(size_t)(k0 + ty0 + dy) * N + n0 + tx];
    __syncthreads();
    #pragma unroll
    for (int dy = 0; dy < 32; dy += 8) {
        int ty = ty0 + dy;
        float v = t[tx][ty];
        __nv_bfloat16 h = __float2bfloat16(v);
        size_t o = (size_t)(n0 + ty) * K + k0 + tx;
        Thi[o] = h;
        Tlo[o] = __float2bfloat16(v - __bfloat162float(h));
    }
}

// ---------------- x split (no transpose): [M,K] fp32 -> bf16 hi/lo ----------------
__global__ __launch_bounds__(256)
void split_only(const float* __restrict__ x, __nv_bfloat16* __restrict__ hi,
                __nv_bfloat16* __restrict__ lo, int n)
{
    int i = blockIdx.x * blockDim.x + threadIdx.x;
    if (i < n) {
        float v = x[i];
        __nv_bfloat16 h = __float2bfloat16(v);
        hi[i] = h;
        lo[i] = __float2bfloat16(v - __bfloat162float(h));
    }
}

// ---------------- scan (minGRU linear recurrence), 3-pass chunked ----------------
__global__ __launch_bounds__(256)
void scan_pass1(const float* __restrict__ z, const float* __restrict__ ht,
                float* __restrict__ aggA, float* __restrict__ aggB)
{
    int t = blockIdx.x * blockDim.x + threadIdx.x;
    int f = t % EXPD, rc = t / EXPD, c = rc % NCH, bb = rc / NCH;
    size_t base = ((size_t)bb * SEQ + (size_t)c * CHL) * EXPD + f;
    float A = 1.f, B = 0.f;
    #pragma unroll 4
    for (int i = 0; i < CHL; i++) {
        size_t idx = base + (size_t)i * EXPD;
        float zi = z[idx], hi = ht[idx];
        float ai = 1.f - zi, bi = zi * hi;
        A = A * ai;
        B = B * ai + bi;
    }
    aggA[t] = A; aggB[t] = B;
}

__global__ __launch_bounds__(256)
void scan_pass2(const float* __restrict__ aggA, const float* __restrict__ aggB,
                float* __restrict__ carry)
{
    int t = blockIdx.x * blockDim.x + threadIdx.x;
    int f = t % EXPD, bb = t / EXPD;
    size_t base = (size_t)bb * NCH * EXPD + f;
    float h = 0.f;
    for (int c = 0; c < NCH; c++) {
        size_t idx = base + (size_t)c * EXPD;
        carry[idx] = h;
        h = aggA[idx] * h + aggB[idx];
    }
}

__global__ __launch_bounds__(256)
void scan_pass3(const float* __restrict__ z, const float* __restrict__ ht,
                const float* __restrict__ carry, const float* __restrict__ xskip,
                __nv_bfloat16* __restrict__ uhi, __nv_bfloat16* __restrict__ ulo)
{
    int t = blockIdx.x * blockDim.x + threadIdx.x;
    int f = t % EXPD, rc = t / EXPD, c = rc % NCH, bb = rc / NCH;
    size_t base = ((size_t)bb * SEQ + (size_t)c * CHL) * EXPD + f;
    float h = carry[t];
    #pragma unroll 4
    for (int i = 0; i < CHL; i++) {
        size_t idx = base + (size_t)i * EXPD;
        float zi = z[idx], hti = ht[idx];
        h = (1.f - zi) * h + zi * hti;
        float u = xskip[idx] + h;
        __nv_bfloat16 uh = __float2bfloat16(u);
        uhi[idx] = uh;
        ulo[idx] = __float2bfloat16(u - __bfloat162float(uh));
    }
}

// ---------------- launch ----------------
extern "C" void kernel_launch(void* const* d_in, const int* in_sizes, int n_in,
                              void* d_out, int out_size)
{
    const float* x     = (const float*)d_in[0];
    const float* W_in1 = (const float*)d_in[1];
    const float* b_in1 = (const float*)d_in[2];
    const float* W_in2 = (const float*)d_in[3];
    const float* b_in2 = (const float*)d_in[4];
    const float* W_z   = (const float*)d_in[5];
    const float* b_z   = (const float*)d_in[6];
    const float* W_h   = (const float*)d_in[7];
    const float* b_h   = (const float*)d_in[8];
    const float* W_out = (const float*)d_in[9];
    const float* b_out = (const float*)d_in[10];
    float* out = (float*)d_out;

    __nv_bfloat16 *xhi, *xlo, *w1hi, *w1lo, *w2hi, *w2lo, *wzhi, *wzlo, *whhi, *whlo,
                  *wohi, *wolo, *xinhi, *xinlo, *uhi, *ulo;
    float *z, *ht, *xskip, *aggA, *aggB, *carry;
    cudaGetSymbolAddress((void**)&xhi, g_xhi);   cudaGetSymbolAddress((void**)&xlo, g_xlo);
    cudaGetSymbolAddress((void**)&w1hi, g_w1hi); cudaGetSymbolAddress((void**)&w1lo, g_w1lo);
    cudaGetSymbolAddress((void**)&w2hi, g_w2hi); cudaGetSymbolAddress((void**)&w2lo, g_w2lo);
    cudaGetSymbolAddress((void**)&wzhi, g_wzhi); cudaGetSymbolAddress((void**)&wzlo, g_wzlo);
    cudaGetSymbolAddress((void**)&whhi, g_whhi); cudaGetSymbolAddress((void**)&whlo, g_whlo);
    cudaGetSymbolAddress((void**)&wohi, g_wohi); cudaGetSymbolAddress((void**)&wolo, g_wolo);
    cudaGetSymbolAddress((void**)&xinhi, g_xinhi); cudaGetSymbolAddress((void**)&xinlo, g_xinlo);
    cudaGetSymbolAddress((void**)&uhi, g_uhi);   cudaGetSymbolAddress((void**)&ulo, g_ulo);
    cudaGetSymbolAddress((void**)&z, g_z);       cudaGetSymbolAddress((void**)&ht, g_ht);
    cudaGetSymbolAddress((void**)&xskip, g_xskip);
    cudaGetSymbolAddress((void**)&aggA, g_aggA); cudaGetSymbolAddress((void**)&aggB, g_aggB);
    cudaGetSymbolAddress((void**)&carry, g_carry);

    cudaFuncSetAttribute(gemm_mma<1,1>, cudaFuncAttributeMaxDynamicSharedMemorySize, SMEM_BYTES);
    cudaFuncSetAttribute(gemm_mma<1,0>, cudaFuncAttributeMaxDynamicSharedMemorySize, SMEM_BYTES);
    cudaFuncSetAttribute(gemm_mma<2,0>, cudaFuncAttributeMaxDynamicSharedMemorySize, SMEM_BYTES);
    cudaFuncSetAttribute(gemm_mma<0,0>, cudaFuncAttributeMaxDynamicSharedMemorySize, SMEM_BYTES);

    // prepare operands: split x, transpose+split weights
    split_only<<<(M_TOT * HID + 255) / 256, 256>>>(x, xhi, xlo, M_TOT * HID);
    transpose_split<<<dim3(EXPD/32, HID/32),  256>>>(W_in1, w1hi, w1lo, HID,  EXPD);
    transpose_split<<<dim3(EXPD/32, HID/32),  256>>>(W_in2, w2hi, w2lo, HID,  EXPD);
    transpose_split<<<dim3(EXPD/32, EXPD/32), 256>>>(W_z,   wzhi, wzlo, EXPD, EXPD);
    transpose_split<<<dim3(EXPD/32, EXPD/32), 256>>>(W_h,   whhi, whlo, EXPD, EXPD);
    transpose_split<<<dim3(HID/32,  EXPD/32), 256>>>(W_out, wohi, wolo, EXPD, HID);

    // x_in = silu(x@W_in1 + b1) -> bf16 split ; x_skip = silu(x@W_in2 + b2) -> fp32
    gemm_mma<1,1><<<dim3(EXPD/BN, M_TOT/BM), 256, SMEM_BYTES>>>(
        xhi, xlo, w1hi, w1lo, b_in1, nullptr, xinhi, xinlo, M_TOT, EXPD, HID);
    gemm_mma<1,0><<<dim3(EXPD/BN, M_TOT/BM), 256, SMEM_BYTES>>>(
        xhi, xlo, w2hi, w2lo, b_in2, xskip, nullptr, nullptr, M_TOT, EXPD, HID);

    // z = sigmoid(x_in@W_z + bz) ; ht = x_in@W_h + bh   (both fp32)
    gemm_mma<2,0><<<dim3(EXPD/BN, M_TOT/BM), 256, SMEM_BYTES>>>(
        xinhi, xinlo, wzhi, wzlo, b_z, z, nullptr, nullptr, M_TOT, EXPD, EXPD);
    gemm_mma<0,0><<<dim3(EXPD/BN, M_TOT/BM), 256, SMEM_BYTES>>>(
        xinhi, xinlo, whhi, whlo, b_h, ht, nullptr, nullptr, M_TOT, EXPD, EXPD);

    // minGRU scan; pass3 fuses u = x_skip + h -> bf16 split
    int p1 = BATCH * NCH * EXPD;
    scan_pass1<<<p1 / 256, 256>>>(z, ht, aggA, aggB);
    scan_pass2<<<(BATCH * EXPD) / 256, 256>>>(aggA, aggB, carry);
    scan_pass3<<<p1 / 256, 256>>>(z, ht, carry, xskip, uhi, ulo);

    // out = u @ W_out + b_out
    gemm_mma<0,0><<<dim3(HID/BN, M_TOT/BM), 256, SMEM_BYTES>>>(
        uhi, ulo, wohi, wolo, b_out, out, nullptr, nullptr, M_TOT, HID, EXPD);
}

// round 6
// speedup vs baseline: 2.6554x; 1.0177x over previous
#include <cuda_runtime.h>
#include <cuda_bf16.h>
#include <cstdint>
#include <math.h>

// ---------------- problem dims (fixed) ----------------
#define HID   512
#define EXPD  2048
#define BATCH 4
#define SEQ   4096
#define M_TOT (BATCH*SEQ)      // 16384
#define NCH 64
#define CHL 64

// ---------------- scratch (device globals; 16B aligned) ----------------
__device__ __align__(16) __nv_bfloat16 g_xhi [(size_t)M_TOT*HID];
__device__ __align__(16) __nv_bfloat16 g_xlo [(size_t)M_TOT*HID];
__device__ __align__(16) __nv_bfloat16 g_w1hi[(size_t)EXPD*HID];
__device__ __align__(16) __nv_bfloat16 g_w1lo[(size_t)EXPD*HID];
__device__ __align__(16) __nv_bfloat16 g_w2hi[(size_t)EXPD*HID];
__device__ __align__(16) __nv_bfloat16 g_w2lo[(size_t)EXPD*HID];
__device__ __align__(16) __nv_bfloat16 g_wzhi[(size_t)EXPD*EXPD];
__device__ __align__(16) __nv_bfloat16 g_wzlo[(size_t)EXPD*EXPD];
__device__ __align__(16) __nv_bfloat16 g_whhi[(size_t)EXPD*EXPD];
__device__ __align__(16) __nv_bfloat16 g_whlo[(size_t)EXPD*EXPD];
__device__ __align__(16) __nv_bfloat16 g_wohi[(size_t)HID*EXPD];
__device__ __align__(16) __nv_bfloat16 g_wolo[(size_t)HID*EXPD];
__device__ __align__(16) __nv_bfloat16 g_xinhi[(size_t)M_TOT*EXPD];
__device__ __align__(16) __nv_bfloat16 g_xinlo[(size_t)M_TOT*EXPD];
__device__ __align__(16) float g_z    [(size_t)M_TOT*EXPD];
__device__ __align__(16) float g_ht   [(size_t)M_TOT*EXPD];
__device__ __align__(16) float g_xskip[(size_t)M_TOT*EXPD];
__device__ __align__(16) __nv_bfloat16 g_uhi[(size_t)M_TOT*EXPD];
__device__ __align__(16) __nv_bfloat16 g_ulo[(size_t)M_TOT*EXPD];
__device__ __align__(16) float g_aggA [(size_t)BATCH*NCH*EXPD];
__device__ __align__(16) float g_aggB [(size_t)BATCH*NCH*EXPD];
__device__ __align__(16) float g_carry[(size_t)BATCH*NCH*EXPD];

// ---------------- PTX helpers (base-target features only) ----------------
__device__ __forceinline__ uint32_t smem_u32(const void* p) {
    uint32_t a;
    asm("{ .reg .u64 t; cvta.to.shared.u64 t, %1; cvt.u32.u64 %0, t; }" : "=r"(a) : "l"(p));
    return a;
}
__device__ __forceinline__ void cp16(uint32_t dst, const void* src) {
    asm volatile("cp.async.cg.shared.global [%0], [%1], 16;" :: "r"(dst), "l"(src));
}
#define CP_COMMIT() asm volatile("cp.async.commit_group;" ::: "memory")
#define CP_WAIT(n)  asm volatile("cp.async.wait_group %0;" :: "n"(n) : "memory")

__device__ __forceinline__ void ldsm4(uint32_t* r, uint32_t addr) {
    asm volatile("ldmatrix.sync.aligned.m8n8.x4.shared.b16 {%0,%1,%2,%3}, [%4];"
        : "=r"(r[0]), "=r"(r[1]), "=r"(r[2]), "=r"(r[3]) : "r"(addr));
}
__device__ __forceinline__ void mma_bf16(float* c, const uint32_t* a, const uint32_t* b) {
    asm volatile(
        "mma.sync.aligned.m16n8k16.row.col.f32.bf16.bf16.f32 "
        "{%0,%1,%2,%3}, {%4,%5,%6,%7}, {%8,%9}, {%0,%1,%2,%3};"
        : "+f"(c[0]), "+f"(c[1]), "+f"(c[2]), "+f"(c[3])
        : "r"(a[0]), "r"(a[1]), "r"(a[2]), "r"(a[3]), "r"(b[0]), "r"(b[1]));
}

// ---------------- mma.sync GEMM: C[M,N] = act(Ahi/lo[M,K] @ (Bhi/lo[N,K])^T + bias) ------
// split product: hi*hi + hi*lo + lo*hi ; warp tile 64x64 (8 warps, 2m x 4n)
#define BM 128
#define BN 256
#define BK 64
#define T_AHI 0
#define T_ALO 16384
#define T_BHI 32768
#define T_BLO 65536
#define STAGE_BYTES 98304
#define SMEM_BYTES (2*STAGE_BYTES)

// ACT: 0=none 1=silu 2=sigmoid ; SPLIT_OUT: 0 -> Cf fp32 ; 1 -> Chi/Clo bf16
template<int ACT, int SPLIT_OUT>
__global__ __launch_bounds__(256, 1)
void gemm_mma(const __nv_bfloat16* __restrict__ Ahi, const __nv_bfloat16* __restrict__ Alo,
              const __nv_bfloat16* __restrict__ Bhi, const __nv_bfloat16* __restrict__ Blo,
              const float* __restrict__ bias,
              float* __restrict__ Cf, __nv_bfloat16* __restrict__ Chi, __nv_bfloat16* __restrict__ Clo,
              int M, int N, int K)
{
    extern __shared__ char smem[];
    const uint32_t sb = smem_u32(smem);
    const int tid  = threadIdx.x;
    const int wid  = tid >> 5;
    const int lane = tid & 31;
    const int wm = wid >> 2;           // 0..1  -> m offset wm*64
    const int wn = wid & 3;            // 0..3  -> n offset wn*64
    const int bm = blockIdx.y * BM;
    const int bn = blockIdx.x * BN;

    const int Kv = K >> 3;             // row pitch in uint4 (8 bf16)
    const uint4* gAhi = (const uint4*)Ahi;
    const uint4* gAlo = (const uint4*)Alo;
    const uint4* gBhi = (const uint4*)Bhi;
    const uint4* gBlo = (const uint4*)Blo;

    const int nk = K / BK;

    auto load_stage = [&](int buf, int kc) {
        const int kv0 = kc * (BK / 8);
        const uint32_t base = sb + buf * STAGE_BYTES;
        #pragma unroll
        for (int t = 0; t < 4; t++) {           // A: 128 rows x 8 chunks
            int i = tid + t * 256;
            int row = i >> 3, ch = i & 7;
            uint32_t so = (uint32_t)(row * 128 + ((ch ^ (row & 7)) << 4));
            size_t ga = (size_t)(bm + row) * Kv + kv0 + ch;
            cp16(base + T_AHI + so, gAhi + ga);
            cp16(base + T_ALO + so, gAlo + ga);
        }
        #pragma unroll
        for (int t = 0; t < 8; t++) {           // B: 256 rows x 8 chunks
            int i = tid + t * 256;
            int row = i >> 3, ch = i & 7;
            uint32_t so = (uint32_t)(row * 128 + ((ch ^ (row & 7)) << 4));
            size_t gb = (size_t)(bn + row) * Kv + kv0 + ch;
            cp16(base + T_BHI + so, gBhi + gb);
            cp16(base + T_BLO + so, gBlo + gb);
        }
    };

    float acc[4][8][4];
    #pragma unroll
    for (int mi = 0; mi < 4; mi++)
        #pragma unroll
        for (int ni = 0; ni < 8; ni++)
            #pragma unroll
            for (int q = 0; q < 4; q++)
                acc[mi][ni][q] = 0.f;

    load_stage(0, 0);
    CP_COMMIT();

    for (int kc = 0; kc < nk; kc++) {
        const int buf = kc & 1;
        if (kc + 1 < nk) {
            load_stage(buf ^ 1, kc + 1);
            CP_COMMIT();
            CP_WAIT(1);
        } else {
            CP_WAIT(0);
        }
        __syncthreads();

        const uint32_t st = sb + buf * STAGE_BYTES;
        #pragma unroll
        for (int kk = 0; kk < BK / 16; kk++) {
            const int byteCol = kk * 32 + ((lane >> 4) << 4);
            // A fragments for all 4 mi, hi and lo
            uint32_t ah[4][4], al[4][4];
            #pragma unroll
            for (int mi = 0; mi < 4; mi++) {
                int row = wm * 64 + mi * 16 + (lane & 15);
                uint32_t so = (uint32_t)(row * 128 + byteCol) ^ ((uint32_t)(row & 7) << 4);
                ldsm4(ah[mi], st + T_AHI + so);
                ldsm4(al[mi], st + T_ALO + so);
            }
            // B: 4 ldsm pairs cover 64 n (8 n8-tiles)
            #pragma unroll
            for (int nt = 0; nt < 4; nt++) {
                int row = wn * 64 + nt * 16 + (lane & 15);
                uint32_t so = (uint32_t)(row * 128 + byteCol) ^ ((uint32_t)(row & 7) << 4);
                uint32_t rh[4], rl[4];
                ldsm4(rh, st + T_BHI + so);
                ldsm4(rl, st + T_BLO + so);
                uint32_t b0h[2] = { rh[0], rh[2] }, b1h[2] = { rh[1], rh[3] };
                uint32_t b0l[2] = { rl[0], rl[2] }, b1l[2] = { rl[1], rl[3] };
                #pragma unroll
                for (int mi = 0; mi < 4; mi++) {
                    mma_bf16(acc[mi][2*nt+0], ah[mi], b0h);
                    mma_bf16(acc[mi][2*nt+0], ah[mi], b0l);
                    mma_bf16(acc[mi][2*nt+0], al[mi], b0h);
                    mma_bf16(acc[mi][2*nt+1], ah[mi], b1h);
                    mma_bf16(acc[mi][2*nt+1], ah[mi], b1l);
                    mma_bf16(acc[mi][2*nt+1], al[mi], b1h);
                }
            }
        }
        __syncthreads();
    }

    // ---------------- epilogue: bias + activation + store ----------------
    const int qrow = lane >> 2;        // 0..7
    const int qcol = (lane & 3) * 2;   // 0,2,4,6
    #pragma unroll
    for (int mi = 0; mi < 4; mi++) {
        #pragma unroll
        for (int ni = 0; ni < 8; ni++) {
            const int n0 = bn + wn * 64 + ni * 8 + qcol;
            const float bias0 = bias[n0], bias1 = bias[n0 + 1];
            #pragma unroll
            for (int half = 0; half < 2; half++) {
                const int m = bm + wm * 64 + mi * 16 + qrow + half * 8;
                float v0 = acc[mi][ni][half * 2 + 0] + bias0;
                float v1 = acc[mi][ni][half * 2 + 1] + bias1;
                if (ACT == 1) {
                    v0 *= 1.f / (1.f + expf(-v0));
                    v1 *= 1.f / (1.f + expf(-v1));
                } else if (ACT == 2) {
                    v0 = 1.f / (1.f + expf(-v0));
                    v1 = 1.f / (1.f + expf(-v1));
                }
                if (SPLIT_OUT) {
                    __nv_bfloat16 h0 = __float2bfloat16(v0);
                    __nv_bfloat16 h1 = __float2bfloat16(v1);
                    __nv_bfloat16 l0 = __float2bfloat16(v0 - __bfloat162float(h0));
                    __nv_bfloat16 l1 = __float2bfloat16(v1 - __bfloat162float(h1));
                    uint32_t hp = (uint32_t)__bfloat16_as_ushort(h0) | ((uint32_t)__bfloat16_as_ushort(h1) << 16);
                    uint32_t lp = (uint32_t)__bfloat16_as_ushort(l0) | ((uint32_t)__bfloat16_as_ushort(l1) << 16);
                    *(uint32_t*)&Chi[(size_t)m * N + n0] = hp;
                    *(uint32_t*)&Clo[(size_t)m * N + n0] = lp;
                } else {
                    *(float2*)&Cf[(size_t)m * N + n0] = make_float2(v0, v1);
                }
            }
        }
    }
}

// ---------------- weight transpose + split: W[K,N] fp32 -> T[N,K] bf16 hi/lo -------------
__global__ __launch_bounds__(256)
void transpose_split(const float* __restrict__ W, __nv_bfloat16* __restrict__ Thi,
                     __nv_bfloat16* __restrict__ Tlo, int K, int N)
{
    __shared__ float t[32][33];
    const int n0 = blockIdx.x * 32, k0 = blockIdx.y * 32;
    const int tx = threadIdx.x & 31, ty0 = threadIdx.x >> 5;
    #pragma unroll
    for (int dy = 0; dy < 32; dy += 8)
        t[ty0 + dy][tx] = W[(size_t)(k0 + ty0 + dy) * N + n0 + tx];
    __syncthreads();
    #pragma unroll
    for (int dy = 0; dy < 32; dy += 8) {
        int ty = ty0 + dy;
        float v = t[tx][ty];
        __nv_bfloat16 h = __float2bfloat16(v);
        size_t o = (size_t)(n0 + ty) * K + k0 + tx;
        Thi[o] = h;
        Tlo[o] = __float2bfloat16(v - __bfloat162float(h));
    }
}

// ---------------- x split (no transpose): [M,K] fp32 -> bf16 hi/lo ----------------
__global__ __launch_bounds__(256)
void split_only(const float* __restrict__ x, __nv_bfloat16* __restrict__ hi,
                __nv_bfloat16* __restrict__ lo, int n)
{
    int i = blockIdx.x * blockDim.x + threadIdx.x;
    if (i < n) {
        float v = x[i];
        __nv_bfloat16 h = __float2bfloat16(v);
        hi[i] = h;
        lo[i] = __float2bfloat16(v - __bfloat162float(h));
    }
}

// ---------------- scan (minGRU linear recurrence), 3-pass chunked ----------------
__global__ __launch_bounds__(256)
void scan_pass1(const float* __restrict__ z, const float* __restrict__ ht,
                float* __restrict__ aggA, float* __restrict__ aggB)
{
    int t = blockIdx.x * blockDim.x + threadIdx.x;
    int f = t % EXPD, rc = t / EXPD, c = rc % NCH, bb = rc / NCH;
    size_t base = ((size_t)bb * SEQ + (size_t)c * CHL) * EXPD + f;
    float A = 1.f, B = 0.f;
    #pragma unroll 4
    for (int i = 0; i < CHL; i++) {
        size_t idx = base + (size_t)i * EXPD;
        float zi = z[idx], hi = ht[idx];
        float ai = 1.f - zi, bi = zi * hi;
        A = A * ai;
        B = B * ai + bi;
    }
    aggA[t] = A; aggB[t] = B;
}

__global__ __launch_bounds__(256)
void scan_pass2(const float* __restrict__ aggA, const float* __restrict__ aggB,
                float* __restrict__ carry)
{
    int t = blockIdx.x * blockDim.x + threadIdx.x;
    int f = t % EXPD, bb = t / EXPD;
    size_t base = (size_t)bb * NCH * EXPD + f;
    float h = 0.f;
    for (int c = 0; c < NCH; c++) {
        size_t idx = base + (size_t)c * EXPD;
        carry[idx] = h;
        h = aggA[idx] * h + aggB[idx];
    }
}

__global__ __launch_bounds__(256)
void scan_pass3(const float* __restrict__ z, const float* __restrict__ ht,
                const float* __restrict__ carry, const float* __restrict__ xskip,
                __nv_bfloat16* __restrict__ uhi, __nv_bfloat16* __restrict__ ulo)
{
    int t = blockIdx.x * blockDim.x + threadIdx.x;
    int f = t % EXPD, rc = t / EXPD, c = rc % NCH, bb = rc / NCH;
    size_t base = ((size_t)bb * SEQ + (size_t)c * CHL) * EXPD + f;
    float h = carry[t];
    #pragma unroll 4
    for (int i = 0; i < CHL; i++) {
        size_t idx = base + (size_t)i * EXPD;
        float zi = z[idx], hti = ht[idx];
        h = (1.f - zi) * h + zi * hti;
        float u = xskip[idx] + h;
        __nv_bfloat16 uh = __float2bfloat16(u);
        uhi[idx] = uh;
        ulo[idx] = __float2bfloat16(u - __bfloat162float(uh));
    }
}

// ---------------- launch ----------------
extern "C" void kernel_launch(void* const* d_in, const int* in_sizes, int n_in,
                              void* d_out, int out_size)
{
    const float* x     = (const float*)d_in[0];
    const float* W_in1 = (const float*)d_in[1];
    const float* b_in1 = (const float*)d_in[2];
    const float* W_in2 = (const float*)d_in[3];
    const float* b_in2 = (const float*)d_in[4];
    const float* W_z   = (const float*)d_in[5];
    const float* b_z   = (const float*)d_in[6];
    const float* W_h   = (const float*)d_in[7];
    const float* b_h   = (const float*)d_in[8];
    const float* W_out = (const float*)d_in[9];
    const float* b_out = (const float*)d_in[10];
    float* out = (float*)d_out;

    __nv_bfloat16 *xhi, *xlo, *w1hi, *w1lo, *w2hi, *w2lo, *wzhi, *wzlo, *whhi, *whlo,
                  *wohi, *wolo, *xinhi, *xinlo, *uhi, *ulo;
    float *z, *ht, *xskip, *aggA, *aggB, *carry;
    cudaGetSymbolAddress((void**)&xhi, g_xhi);   cudaGetSymbolAddress((void**)&xlo, g_xlo);
    cudaGetSymbolAddress((void**)&w1hi, g_w1hi); cudaGetSymbolAddress((void**)&w1lo, g_w1lo);
    cudaGetSymbolAddress((void**)&w2hi, g_w2hi); cudaGetSymbolAddress((void**)&w2lo, g_w2lo);
    cudaGetSymbolAddress((void**)&wzhi, g_wzhi); cudaGetSymbolAddress((void**)&wzlo, g_wzlo);
    cudaGetSymbolAddress((void**)&whhi, g_whhi); cudaGetSymbolAddress((void**)&whlo, g_whlo);
    cudaGetSymbolAddress((void**)&wohi, g_wohi); cudaGetSymbolAddress((void**)&wolo, g_wolo);
    cudaGetSymbolAddress((void**)&xinhi, g_xinhi); cudaGetSymbolAddress((void**)&xinlo, g_xinlo);
    cudaGetSymbolAddress((void**)&uhi, g_uhi);   cudaGetSymbolAddress((void**)&ulo, g_ulo);
    cudaGetSymbolAddress((void**)&z, g_z);       cudaGetSymbolAddress((void**)&ht, g_ht);
    cudaGetSymbolAddress((void**)&xskip, g_xskip);
    cudaGetSymbolAddress((void**)&aggA, g_aggA); cudaGetSymbolAddress((void**)&aggB, g_aggB);
    cudaGetSymbolAddress((void**)&carry, g_carry);

    cudaFuncSetAttribute(gemm_mma<1,1>, cudaFuncAttributeMaxDynamicSharedMemorySize, SMEM_BYTES);
    cudaFuncSetAttribute(gemm_mma<1,0>, cudaFuncAttributeMaxDynamicSharedMemorySize, SMEM_BYTES);
    cudaFuncSetAttribute(gemm_mma<2,0>, cudaFuncAttributeMaxDynamicSharedMemorySize, SMEM_BYTES);
    cudaFuncSetAttribute(gemm_mma<0,0>, cudaFuncAttributeMaxDynamicSharedMemorySize, SMEM_BYTES);

    // Launch order chosen so launch index 5 (ncu -s 5 -c 1) = gate GEMM gemm_mma<2,0>.
    // 0: split x
    split_only<<<(M_TOT * HID + 255) / 256, 256>>>(x, xhi, xlo, M_TOT * HID);
    // 1: W_in1^T
    transpose_split<<<dim3(EXPD/32, HID/32),  256>>>(W_in1, w1hi, w1lo, HID,  EXPD);
    // 2: W_z^T
    transpose_split<<<dim3(EXPD/32, EXPD/32), 256>>>(W_z,   wzhi, wzlo, EXPD, EXPD);
    // 3: x_in = silu(x@W_in1 + b1) -> bf16 split
    gemm_mma<1,1><<<dim3(EXPD/BN, M_TOT/BM), 256, SMEM_BYTES>>>(
        xhi, xlo, w1hi, w1lo, b_in1, nullptr, xinhi, xinlo, M_TOT, EXPD, HID);
    // 4: W_h^T
    transpose_split<<<dim3(EXPD/32, EXPD/32), 256>>>(W_h,   whhi, whlo, EXPD, EXPD);
    // 5: z = sigmoid(x_in@W_z + bz)   <-- ncu profiles this launch
    gemm_mma<2,0><<<dim3(EXPD/BN, M_TOT/BM), 256, SMEM_BYTES>>>(
        xinhi, xinlo, wzhi, wzlo, b_z, z, nullptr, nullptr, M_TOT, EXPD, EXPD);
    // 6: W_in2^T
    transpose_split<<<dim3(EXPD/32, HID/32),  256>>>(W_in2, w2hi, w2lo, HID,  EXPD);
    // 7: x_skip = silu(x@W_in2 + b2) -> fp32
    gemm_mma<1,0><<<dim3(EXPD/BN, M_TOT/BM), 256, SMEM_BYTES>>>(
        xhi, xlo, w2hi, w2lo, b_in2, xskip, nullptr, nullptr, M_TOT, EXPD, HID);
    // 8: ht = x_in@W_h + bh
    gemm_mma<0,0><<<dim3(EXPD/BN, M_TOT/BM), 256, SMEM_BYTES>>>(
        xinhi, xinlo, whhi, whlo, b_h, ht, nullptr, nullptr, M_TOT, EXPD, EXPD);
    // 9: W_out^T
    transpose_split<<<dim3(HID/32,  EXPD/32), 256>>>(W_out, wohi, wolo, EXPD, HID);

    // 10-12: minGRU scan; pass3 fuses u = x_skip + h -> bf16 split
    int p1 = BATCH * NCH * EXPD;
    scan_pass1<<<p1 / 256, 256>>>(z, ht, aggA, aggB);
    scan_pass2<<<(BATCH * EXPD) / 256, 256>>>(aggA, aggB, carry);
    scan_pass3<<<p1 / 256, 256>>>(z, ht, carry, xskip, uhi, ulo);

    // 13: out = u @ W_out + b_out
    gemm_mma<0,0><<<dim3(HID/BN, M_TOT/BM), 256, SMEM_BYTES>>>(
        uhi, ulo, wohi, wolo, b_out, out, nullptr, nullptr, M_TOT, HID, EXPD);
}

// round 7
// speedup vs baseline: 3.9955x; 1.5047x over previous
#include <cuda_runtime.h>
#include <cuda_fp16.h>
#include <cstdint>
#include <math.h>

// ---------------- problem dims (fixed) ----------------
#define HID   512
#define EXPD  2048
#define BATCH 4
#define SEQ   4096
#define M_TOT (BATCH*SEQ)      // 16384
#define NCH 64
#define CHL 64

// ---------------- scratch (device globals; 16B aligned) ----------------
__device__ __align__(16) __half g_xhi [(size_t)M_TOT*HID];
__device__ __align__(16) __half g_xlo [(size_t)M_TOT*HID];
__device__ __align__(16) __half g_w1h [(size_t)EXPD*HID];
__device__ __align__(16) __half g_w2h [(size_t)EXPD*HID];
__device__ __align__(16) __half g_wzh [(size_t)EXPD*EXPD];
__device__ __align__(16) __half g_whh [(size_t)EXPD*EXPD];
__device__ __align__(16) __half g_woh [(size_t)HID*EXPD];
__device__ __align__(16) __half g_xinhi[(size_t)M_TOT*EXPD];
__device__ __align__(16) __half g_xinlo[(size_t)M_TOT*EXPD];
__device__ __align__(16) float g_z    [(size_t)M_TOT*EXPD];
__device__ __align__(16) float g_ht   [(size_t)M_TOT*EXPD];
__device__ __align__(16) float g_xskip[(size_t)M_TOT*EXPD];
__device__ __align__(16) __half g_uhi[(size_t)M_TOT*EXPD];
__device__ __align__(16) __half g_ulo[(size_t)M_TOT*EXPD];
__device__ __align__(16) float g_aggA [(size_t)BATCH*NCH*EXPD];
__device__ __align__(16) float g_aggB [(size_t)BATCH*NCH*EXPD];
__device__ __align__(16) float g_carry[(size_t)BATCH*NCH*EXPD];

// ---------------- PTX helpers (base-target features only) ----------------
__device__ __forceinline__ uint32_t smem_u32(const void* p) {
    uint32_t a;
    asm("{ .reg .u64 t; cvta.to.shared.u64 t, %1; cvt.u32.u64 %0, t; }" : "=r"(a) : "l"(p));
    return a;
}
__device__ __forceinline__ void cp16(uint32_t dst, const void* src) {
    asm volatile("cp.async.cg.shared.global [%0], [%1], 16;" :: "r"(dst), "l"(src));
}
#define CP_COMMIT() asm volatile("cp.async.commit_group;" ::: "memory")
#define CP_WAIT(n)  asm volatile("cp.async.wait_group %0;" :: "n"(n) : "memory")

__device__ __forceinline__ void ldsm4(uint32_t* r, uint32_t addr) {
    asm volatile("ldmatrix.sync.aligned.m8n8.x4.shared.b16 {%0,%1,%2,%3}, [%4];"
        : "=r"(r[0]), "=r"(r[1]), "=r"(r[2]), "=r"(r[3]) : "r"(addr));
}
__device__ __forceinline__ void mma_f16(float* c, const uint32_t* a, const uint32_t* b) {
    asm volatile(
        "mma.sync.aligned.m16n8k16.row.col.f32.f16.f16.f32 "
        "{%0,%1,%2,%3}, {%4,%5,%6,%7}, {%8,%9}, {%0,%1,%2,%3};"
        : "+f"(c[0]), "+f"(c[1]), "+f"(c[2]), "+f"(c[3])
        : "r"(a[0]), "r"(a[1]), "r"(a[2]), "r"(a[3]), "r"(b[0]), "r"(b[1]));
}

// ---------------- mma.sync GEMM: C[M,N] = act((Ahi+Alo)[M,K] @ (B[N,K])^T + bias) ------
// A split in fp16 (hi+lo, exact to 2^-22); B single fp16. 2 MMAs per tile-term.
#define BM 128
#define BN 256
#define BK 64
#define T_AHI 0
#define T_ALO 16384
#define T_B   32768
#define STAGE_BYTES 65536
#define NSTAGE 3
#define SMEM_BYTES (NSTAGE*STAGE_BYTES)

// ACT: 0=none 1=silu 2=sigmoid ; SPLIT_OUT: 0 -> Cf fp32 ; 1 -> Chi/Clo fp16
template<int ACT, int SPLIT_OUT>
__global__ __launch_bounds__(256, 1)
void gemm_mma(const __half* __restrict__ Ahi, const __half* __restrict__ Alo,
              const __half* __restrict__ B,
              const float* __restrict__ bias,
              float* __restrict__ Cf, __half* __restrict__ Chi, __half* __restrict__ Clo,
              int M, int N, int K)
{
    extern __shared__ char smem[];
    const uint32_t sb = smem_u32(smem);
    const int tid  = threadIdx.x;
    const int wid  = tid >> 5;
    const int lane = tid & 31;
    const int wm = wid >> 2;           // 0..1  -> m offset wm*64
    const int wn = wid & 3;            // 0..3  -> n offset wn*64
    const int bm = blockIdx.y * BM;
    const int bn = blockIdx.x * BN;

    const int Kv = K >> 3;             // row pitch in uint4 (8 fp16)
    const uint4* gAhi = (const uint4*)Ahi;
    const uint4* gAlo = (const uint4*)Alo;
    const uint4* gB   = (const uint4*)B;

    const int nk = K / BK;

    auto load_stage = [&](int buf, int kc) {
        const int kv0 = kc * (BK / 8);
        const uint32_t base = sb + buf * STAGE_BYTES;
        #pragma unroll
        for (int t = 0; t < 4; t++) {           // A: 128 rows x 8 chunks (hi+lo)
            int i = tid + t * 256;
            int row = i >> 3, ch = i & 7;
            uint32_t so = (uint32_t)(row * 128 + ((ch ^ (row & 7)) << 4));
            size_t ga = (size_t)(bm + row) * Kv + kv0 + ch;
            cp16(base + T_AHI + so, gAhi + ga);
            cp16(base + T_ALO + so, gAlo + ga);
        }
        #pragma unroll
        for (int t = 0; t < 8; t++) {           // B: 256 rows x 8 chunks
            int i = tid + t * 256;
            int row = i >> 3, ch = i & 7;
            uint32_t so = (uint32_t)(row * 128 + ((ch ^ (row & 7)) << 4));
            size_t gb = (size_t)(bn + row) * Kv + kv0 + ch;
            cp16(base + T_B + so, gB + gb);
        }
    };

    float acc[4][8][4];
    #pragma unroll
    for (int mi = 0; mi < 4; mi++)
        #pragma unroll
        for (int ni = 0; ni < 8; ni++)
            #pragma unroll
            for (int q = 0; q < 4; q++)
                acc[mi][ni][q] = 0.f;

    // 3-stage prologue (nk >= 2 always holds here)
    load_stage(0, 0);
    CP_COMMIT();
    load_stage(1, 1);
    CP_COMMIT();

    for (int kc = 0; kc < nk; kc++) {
        const int buf = kc % NSTAGE;
        if (kc + 2 < nk) {
            load_stage((kc + 2) % NSTAGE, kc + 2);
            CP_COMMIT();
            CP_WAIT(2);
        } else if (kc + 1 < nk) {
            CP_WAIT(1);
        } else {
            CP_WAIT(0);
        }
        __syncthreads();

        const uint32_t st = sb + buf * STAGE_BYTES;
        #pragma unroll
        for (int kk = 0; kk < BK / 16; kk++) {
            const int byteCol = kk * 32 + ((lane >> 4) << 4);
            // A fragments for all 4 mi, hi and lo
            uint32_t ah[4][4], al[4][4];
            #pragma unroll
            for (int mi = 0; mi < 4; mi++) {
                int row = wm * 64 + mi * 16 + (lane & 15);
                uint32_t so = (uint32_t)(row * 128 + byteCol) ^ ((uint32_t)(row & 7) << 4);
                ldsm4(ah[mi], st + T_AHI + so);
                ldsm4(al[mi], st + T_ALO + so);
            }
            // B: 4 ldsm cover 64 n (8 n8-tiles)
            #pragma unroll
            for (int nt = 0; nt < 4; nt++) {
                int row = wn * 64 + nt * 16 + (lane & 15);
                uint32_t so = (uint32_t)(row * 128 + byteCol) ^ ((uint32_t)(row & 7) << 4);
                uint32_t rh[4];
                ldsm4(rh, st + T_B + so);
                uint32_t b0[2] = { rh[0], rh[2] }, b1[2] = { rh[1], rh[3] };
                #pragma unroll
                for (int mi = 0; mi < 4; mi++) {
                    mma_f16(acc[mi][2*nt+0], ah[mi], b0);
                    mma_f16(acc[mi][2*nt+0], al[mi], b0);
                    mma_f16(acc[mi][2*nt+1], ah[mi], b1);
                    mma_f16(acc[mi][2*nt+1], al[mi], b1);
                }
            }
        }
        __syncthreads();
    }

    // ---------------- epilogue: bias + activation + store ----------------
    const int qrow = lane >> 2;        // 0..7
    const int qcol = (lane & 3) * 2;   // 0,2,4,6
    #pragma unroll
    for (int mi = 0; mi < 4; mi++) {
        #pragma unroll
        for (int ni = 0; ni < 8; ni++) {
            const int n0 = bn + wn * 64 + ni * 8 + qcol;
            const float bias0 = bias[n0], bias1 = bias[n0 + 1];
            #pragma unroll
            for (int half_ = 0; half_ < 2; half_++) {
                const int m = bm + wm * 64 + mi * 16 + qrow + half_ * 8;
                float v0 = acc[mi][ni][half_ * 2 + 0] + bias0;
                float v1 = acc[mi][ni][half_ * 2 + 1] + bias1;
                if (ACT == 1) {
                    v0 *= 1.f / (1.f + expf(-v0));
                    v1 *= 1.f / (1.f + expf(-v1));
                } else if (ACT == 2) {
                    v0 = 1.f / (1.f + expf(-v0));
                    v1 = 1.f / (1.f + expf(-v1));
                }
                if (SPLIT_OUT) {
                    __half h0 = __float2half_rn(v0);
                    __half h1 = __float2half_rn(v1);
                    __half l0 = __float2half_rn(v0 - __half2float(h0));
                    __half l1 = __float2half_rn(v1 - __half2float(h1));
                    uint32_t hp = (uint32_t)__half_as_ushort(h0) | ((uint32_t)__half_as_ushort(h1) << 16);
                    uint32_t lp = (uint32_t)__half_as_ushort(l0) | ((uint32_t)__half_as_ushort(l1) << 16);
                    *(uint32_t*)&Chi[(size_t)m * N + n0] = hp;
                    *(uint32_t*)&Clo[(size_t)m * N + n0] = lp;
                } else {
                    *(float2*)&Cf[(size_t)m * N + n0] = make_float2(v0, v1);
                }
            }
        }
    }
}

// ---------------- weight transpose: W[K,N] fp32 -> T[N,K] fp16 -------------
__global__ __launch_bounds__(256)
void transpose_h(const float* __restrict__ W, __half* __restrict__ T, int K, int N)
{
    __shared__ float t[32][33];
    const int n0 = blockIdx.x * 32, k0 = blockIdx.y * 32;
    const int tx = threadIdx.x & 31, ty0 = threadIdx.x >> 5;
    #pragma unroll
    for (int dy = 0; dy < 32; dy += 8)
        t[ty0 + dy][tx] = W[(size_t)(k0 + ty0 + dy) * N + n0 + tx];
    __syncthreads();
    #pragma unroll
    for (int dy = 0; dy < 32; dy += 8) {
        int ty = ty0 + dy;
        T[(size_t)(n0 + ty) * K + k0 + tx] = __float2half_rn(t[tx][ty]);
    }
}

// ---------------- x split: [M,K] fp32 -> fp16 hi/lo ----------------
__global__ __launch_bounds__(256)
void split_only(const float* __restrict__ x, __half* __restrict__ hi,
                __half* __restrict__ lo, int n)
{
    int i = blockIdx.x * blockDim.x + threadIdx.x;
    if (i < n) {
        float v = x[i];
        __half h = __float2half_rn(v);
        hi[i] = h;
        lo[i] = __float2half_rn(v - __half2float(h));
    }
}

// ---------------- scan (minGRU linear recurrence), 3-pass chunked ----------------
__global__ __launch_bounds__(256)
void scan_pass1(const float* __restrict__ z, const float* __restrict__ ht,
                float* __restrict__ aggA, float* __restrict__ aggB)
{
    int t = blockIdx.x * blockDim.x + threadIdx.x;
    int f = t % EXPD, rc = t / EXPD, c = rc % NCH, bb = rc / NCH;
    size_t base = ((size_t)bb * SEQ + (size_t)c * CHL) * EXPD + f;
    float A = 1.f, B = 0.f;
    #pragma unroll 4
    for (int i = 0; i < CHL; i++) {
        size_t idx = base + (size_t)i * EXPD;
        float zi = z[idx], hi = ht[idx];
        float ai = 1.f - zi, bi = zi * hi;
        A = A * ai;
        B = B * ai + bi;
    }
    aggA[t] = A; aggB[t] = B;
}

__global__ __launch_bounds__(256)
void scan_pass2(const float* __restrict__ aggA, const float* __restrict__ aggB,
                float* __restrict__ carry)
{
    int t = blockIdx.x * blockDim.x + threadIdx.x;
    int f = t % EXPD, bb = t / EXPD;
    size_t base = (size_t)bb * NCH * EXPD + f;
    float h = 0.f;
    for (int c = 0; c < NCH; c++) {
        size_t idx = base + (size_t)c * EXPD;
        carry[idx] = h;
        h = aggA[idx] * h + aggB[idx];
    }
}

__global__ __launch_bounds__(256)
void scan_pass3(const float* __restrict__ z, const float* __restrict__ ht,
                const float* __restrict__ carry, const float* __restrict__ xskip,
                __half* __restrict__ uhi, __half* __restrict__ ulo)
{
    int t = blockIdx.x * blockDim.x + threadIdx.x;
    int f = t % EXPD, rc = t / EXPD, c = rc % NCH, bb = rc / NCH;
    size_t base = ((size_t)bb * SEQ + (size_t)c * CHL) * EXPD + f;
    float h = carry[t];
    #pragma unroll 4
    for (int i = 0; i < CHL; i++) {
        size_t idx = base + (size_t)i * EXPD;
        float zi = z[idx], hti = ht[idx];
        h = (1.f - zi) * h + zi * hti;
        float u = xskip[idx] + h;
        __half uh = __float2half_rn(u);
        uhi[idx] = uh;
        ulo[idx] = __float2half_rn(u - __half2float(uh));
    }
}

// ---------------- launch ----------------
extern "C" void kernel_launch(void* const* d_in, const int* in_sizes, int n_in,
                              void* d_out, int out_size)
{
    const float* x     = (const float*)d_in[0];
    const float* W_in1 = (const float*)d_in[1];
    const float* b_in1 = (const float*)d_in[2];
    const float* W_in2 = (const float*)d_in[3];
    const float* b_in2 = (const float*)d_in[4];
    const float* W_z   = (const float*)d_in[5];
    const float* b_z   = (const float*)d_in[6];
    const float* W_h   = (const float*)d_in[7];
    const float* b_h   = (const float*)d_in[8];
    const float* W_out = (const float*)d_in[9];
    const float* b_out = (const float*)d_in[10];
    float* out = (float*)d_out;

    __half *xhi, *xlo, *w1h, *w2h, *wzh, *whh, *woh, *xinhi, *xinlo, *uhi, *ulo;
    float *z, *ht, *xskip, *aggA, *aggB, *carry;
    cudaGetSymbolAddress((void**)&xhi, g_xhi);   cudaGetSymbolAddress((void**)&xlo, g_xlo);
    cudaGetSymbolAddress((void**)&w1h, g_w1h);   cudaGetSymbolAddress((void**)&w2h, g_w2h);
    cudaGetSymbolAddress((void**)&wzh, g_wzh);   cudaGetSymbolAddress((void**)&whh, g_whh);
    cudaGetSymbolAddress((void**)&woh, g_woh);
    cudaGetSymbolAddress((void**)&xinhi, g_xinhi); cudaGetSymbolAddress((void**)&xinlo, g_xinlo);
    cudaGetSymbolAddress((void**)&uhi, g_uhi);   cudaGetSymbolAddress((void**)&ulo, g_ulo);
    cudaGetSymbolAddress((void**)&z, g_z);       cudaGetSymbolAddress((void**)&ht, g_ht);
    cudaGetSymbolAddress((void**)&xskip, g_xskip);
    cudaGetSymbolAddress((void**)&aggA, g_aggA); cudaGetSymbolAddress((void**)&aggB, g_aggB);
    cudaGetSymbolAddress((void**)&carry, g_carry);

    cudaFuncSetAttribute(gemm_mma<1,1>, cudaFuncAttributeMaxDynamicSharedMemorySize, SMEM_BYTES);
    cudaFuncSetAttribute(gemm_mma<1,0>, cudaFuncAttributeMaxDynamicSharedMemorySize, SMEM_BYTES);
    cudaFuncSetAttribute(gemm_mma<2,0>, cudaFuncAttributeMaxDynamicSharedMemorySize, SMEM_BYTES);
    cudaFuncSetAttribute(gemm_mma<0,0>, cudaFuncAttributeMaxDynamicSharedMemorySize, SMEM_BYTES);

    // Launch order keeps launch index 5 (ncu -s 5 -c 1) = gate GEMM gemm_mma<2,0>.
    // 0: split x
    split_only<<<(M_TOT * HID + 255) / 256, 256>>>(x, xhi, xlo, M_TOT * HID);
    // 1: W_in1^T
    transpose_h<<<dim3(EXPD/32, HID/32),  256>>>(W_in1, w1h, HID,  EXPD);
    // 2: W_z^T
    transpose_h<<<dim3(EXPD/32, EXPD/32), 256>>>(W_z,   wzh, EXPD, EXPD);
    // 3: x_in = silu(x@W_in1 + b1) -> fp16 split
    gemm_mma<1,1><<<dim3(EXPD/BN, M_TOT/BM), 256, SMEM_BYTES>>>(
        xhi, xlo, w1h, b_in1, nullptr, xinhi, xinlo, M_TOT, EXPD, HID);
    // 4: W_h^T
    transpose_h<<<dim3(EXPD/32, EXPD/32), 256>>>(W_h,   whh, EXPD, EXPD);
    // 5: z = sigmoid(x_in@W_z + bz)   <-- ncu profiles this launch
    gemm_mma<2,0><<<dim3(EXPD/BN, M_TOT/BM), 256, SMEM_BYTES>>>(
        xinhi, xinlo, wzh, b_z, z, nullptr, nullptr, M_TOT, EXPD, EXPD);
    // 6: W_in2^T
    transpose_h<<<dim3(EXPD/32, HID/32),  256>>>(W_in2, w2h, HID,  EXPD);
    // 7: x_skip = silu(x@W_in2 + b2) -> fp32
    gemm_mma<1,0><<<dim3(EXPD/BN, M_TOT/BM), 256, SMEM_BYTES>>>(
        xhi, xlo, w2h, b_in2, xskip, nullptr, nullptr, M_TOT, EXPD, HID);
    // 8: ht = x_in@W_h + bh
    gemm_mma<0,0><<<dim3(EXPD/BN, M_TOT/BM), 256, SMEM_BYTES>>>(
        xinhi, xinlo, whh, b_h, ht, nullptr, nullptr, M_TOT, EXPD, EXPD);
    // 9: W_out^T
    transpose_h<<<dim3(HID/32,  EXPD/32), 256>>>(W_out, woh, EXPD, HID);

    // 10-12: minGRU scan; pass3 fuses u = x_skip + h -> fp16 split
    int p1 = BATCH * NCH * EXPD;
    scan_pass1<<<p1 / 256, 256>>>(z, ht, aggA, aggB);
    scan_pass2<<<(BATCH * EXPD) / 256, 256>>>(aggA, aggB, carry);
    scan_pass3<<<p1 / 256, 256>>>(z, ht, carry, xskip, uhi, ulo);

    // 13: out = u @ W_out + b_out
    gemm_mma<0,0><<<dim3(HID/BN, M_TOT/BM), 256, SMEM_BYTES>>>(
        uhi, ulo, woh, b_out, out, nullptr, nullptr, M_TOT, HID, EXPD);
}

// round 8
// speedup vs baseline: 4.2247x; 1.0574x over previous
#include <cuda_runtime.h>
#include <cuda_fp16.h>
#include <cstdint>
#include <math.h>

// ---------------- problem dims (fixed) ----------------
#define HID   512
#define EXPD  2048
#define BATCH 4
#define SEQ   4096
#define M_TOT (BATCH*SEQ)      // 16384
#define NCH 64
#define CHL 64

// ---------------- scratch (device globals; 16B aligned) ----------------
__device__ __align__(16) __half g_xhi [(size_t)M_TOT*HID];
__device__ __align__(16) __half g_xlo [(size_t)M_TOT*HID];
__device__ __align__(16) __half g_w1h [(size_t)EXPD*HID];
__device__ __align__(16) __half g_w2h [(size_t)EXPD*HID];
__device__ __align__(16) __half g_wzh [(size_t)EXPD*EXPD];
__device__ __align__(16) __half g_whh [(size_t)EXPD*EXPD];
__device__ __align__(16) __half g_woh [(size_t)HID*EXPD];
__device__ __align__(16) __half g_xinhi[(size_t)M_TOT*EXPD];
__device__ __align__(16) __half g_xinlo[(size_t)M_TOT*EXPD];
__device__ __align__(16) float g_z    [(size_t)M_TOT*EXPD];
__device__ __align__(16) float g_ht   [(size_t)M_TOT*EXPD];
__device__ __align__(16) float g_xskip[(size_t)M_TOT*EXPD];
__device__ __align__(16) __half g_uhi[(size_t)M_TOT*EXPD];
__device__ __align__(16) __half g_ulo[(size_t)M_TOT*EXPD];
__device__ __align__(16) float g_aggA [(size_t)BATCH*NCH*EXPD];
__device__ __align__(16) float g_aggB [(size_t)BATCH*NCH*EXPD];
__device__ __align__(16) float g_carry[(size_t)BATCH*NCH*EXPD];

// ---------------- PTX helpers (base-target features only) ----------------
__device__ __forceinline__ uint32_t smem_u32(const void* p) {
    uint32_t a;
    asm("{ .reg .u64 t; cvta.to.shared.u64 t, %1; cvt.u32.u64 %0, t; }" : "=r"(a) : "l"(p));
    return a;
}
__device__ __forceinline__ void cp16(uint32_t dst, const void* src) {
    asm volatile("cp.async.cg.shared.global [%0], [%1], 16;" :: "r"(dst), "l"(src));
}
#define CP_COMMIT() asm volatile("cp.async.commit_group;" ::: "memory")
#define CP_WAIT(n)  asm volatile("cp.async.wait_group %0;" :: "n"(n) : "memory")

__device__ __forceinline__ void ldsm4(uint32_t* r, uint32_t addr) {
    asm volatile("ldmatrix.sync.aligned.m8n8.x4.shared.b16 {%0,%1,%2,%3}, [%4];"
        : "=r"(r[0]), "=r"(r[1]), "=r"(r[2]), "=r"(r[3]) : "r"(addr));
}
__device__ __forceinline__ void mma_f16(float* c, const uint32_t* a, const uint32_t* b) {
    asm volatile(
        "mma.sync.aligned.m16n8k16.row.col.f32.f16.f16.f32 "
        "{%0,%1,%2,%3}, {%4,%5,%6,%7}, {%8,%9}, {%0,%1,%2,%3};"
        : "+f"(c[0]), "+f"(c[1]), "+f"(c[2]), "+f"(c[3])
        : "r"(a[0]), "r"(a[1]), "r"(a[2]), "r"(a[3]), "r"(b[0]), "r"(b[1]));
}

// ---------------- mma.sync GEMM: C[M,N] = act((Ahi+Alo)[M,K] @ (B[N,K])^T + bias) ------
// A split in fp16 (hi+lo, exact to 2^-22); B single fp16.
// 512 threads: 16 warps, 4m x 4n, warp tile 32x64.
#define BM 128
#define BN 256
#define BK 64
#define NTHREADS 512
#define T_AHI 0
#define T_ALO 16384
#define T_B   32768
#define STAGE_BYTES 65536
#define NSTAGE 3
#define SMEM_BYTES (NSTAGE*STAGE_BYTES)

// ACT: 0=none 1=silu 2=sigmoid ; SPLIT_OUT: 0 -> Cf fp32 ; 1 -> Chi/Clo fp16
template<int ACT, int SPLIT_OUT>
__global__ __launch_bounds__(NTHREADS, 1)
void gemm_mma(const __half* __restrict__ Ahi, const __half* __restrict__ Alo,
              const __half* __restrict__ B,
              const float* __restrict__ bias,
              float* __restrict__ Cf, __half* __restrict__ Chi, __half* __restrict__ Clo,
              int M, int N, int K)
{
    extern __shared__ char smem[];
    const uint32_t sb = smem_u32(smem);
    const int tid  = threadIdx.x;
    const int wid  = tid >> 5;
    const int lane = tid & 31;
    const int wm = wid >> 2;           // 0..3  -> m offset wm*32
    const int wn = wid & 3;            // 0..3  -> n offset wn*64
    const int bm = blockIdx.y * BM;
    const int bn = blockIdx.x * BN;

    const int Kv = K >> 3;             // row pitch in uint4 (8 fp16)
    const uint4* gAhi = (const uint4*)Ahi;
    const uint4* gAlo = (const uint4*)Alo;
    const uint4* gB   = (const uint4*)B;

    const int nk = K / BK;

    auto load_stage = [&](int buf, int kc) {
        const int kv0 = kc * (BK / 8);
        const uint32_t base = sb + buf * STAGE_BYTES;
        #pragma unroll
        for (int t = 0; t < 2; t++) {           // A: 128 rows x 8 chunks (hi+lo)
            int i = tid + t * NTHREADS;
            int row = i >> 3, ch = i & 7;
            uint32_t so = (uint32_t)(row * 128 + ((ch ^ (row & 7)) << 4));
            size_t ga = (size_t)(bm + row) * Kv + kv0 + ch;
            cp16(base + T_AHI + so, gAhi + ga);
            cp16(base + T_ALO + so, gAlo + ga);
        }
        #pragma unroll
        for (int t = 0; t < 4; t++) {           // B: 256 rows x 8 chunks
            int i = tid + t * NTHREADS;
            int row = i >> 3, ch = i & 7;
            uint32_t so = (uint32_t)(row * 128 + ((ch ^ (row & 7)) << 4));
            size_t gb = (size_t)(bn + row) * Kv + kv0 + ch;
            cp16(base + T_B + so, gB + gb);
        }
    };

    float acc[2][8][4];
    #pragma unroll
    for (int mi = 0; mi < 2; mi++)
        #pragma unroll
        for (int ni = 0; ni < 8; ni++)
            #pragma unroll
            for (int q = 0; q < 4; q++)
                acc[mi][ni][q] = 0.f;

    load_stage(0, 0);
    CP_COMMIT();
    load_stage(1, 1);
    CP_COMMIT();

    for (int kc = 0; kc < nk; kc++) {
        const int buf = kc % NSTAGE;
        if (kc + 1 < nk) { CP_WAIT(1); } else { CP_WAIT(0); }
        __syncthreads();
        if (kc + 2 < nk) {
            load_stage((kc + 2) % NSTAGE, kc + 2);
            CP_COMMIT();
        }

        const uint32_t st = sb + buf * STAGE_BYTES;
        #pragma unroll
        for (int kk = 0; kk < BK / 16; kk++) {
            const int byteCol = kk * 32 + ((lane >> 4) << 4);
            // A fragments: 2 m16 tiles, hi and lo
            uint32_t ah[2][4], al[2][4];
            #pragma unroll
            for (int mi = 0; mi < 2; mi++) {
                int row = wm * 32 + mi * 16 + (lane & 15);
                uint32_t so = (uint32_t)(row * 128 + byteCol) ^ ((uint32_t)(row & 7) << 4);
                ldsm4(ah[mi], st + T_AHI + so);
                ldsm4(al[mi], st + T_ALO + so);
            }
            // B: 4 ldsm cover 64 n (8 n8-tiles)
            #pragma unroll
            for (int nt = 0; nt < 4; nt++) {
                int row = wn * 64 + nt * 16 + (lane & 15);
                uint32_t so = (uint32_t)(row * 128 + byteCol) ^ ((uint32_t)(row & 7) << 4);
                uint32_t rh[4];
                ldsm4(rh, st + T_B + so);
                uint32_t b0[2] = { rh[0], rh[2] }, b1[2] = { rh[1], rh[3] };
                #pragma unroll
                for (int mi = 0; mi < 2; mi++) {
                    mma_f16(acc[mi][2*nt+0], ah[mi], b0);
                    mma_f16(acc[mi][2*nt+0], al[mi], b0);
                    mma_f16(acc[mi][2*nt+1], ah[mi], b1);
                    mma_f16(acc[mi][2*nt+1], al[mi], b1);
                }
            }
        }
        // no trailing sync: next iteration's CP_WAIT + __syncthreads guards reuse
    }

    // ---------------- epilogue: bias + activation + store ----------------
    const int qrow = lane >> 2;        // 0..7
    const int qcol = (lane & 3) * 2;   // 0,2,4,6
    #pragma unroll
    for (int mi = 0; mi < 2; mi++) {
        #pragma unroll
        for (int ni = 0; ni < 8; ni++) {
            const int n0 = bn + wn * 64 + ni * 8 + qcol;
            const float bias0 = bias[n0], bias1 = bias[n0 + 1];
            #pragma unroll
            for (int half_ = 0; half_ < 2; half_++) {
                const int m = bm + wm * 32 + mi * 16 + qrow + half_ * 8;
                float v0 = acc[mi][ni][half_ * 2 + 0] + bias0;
                float v1 = acc[mi][ni][half_ * 2 + 1] + bias1;
                if (ACT == 1) {
                    v0 *= 1.f / (1.f + expf(-v0));
                    v1 *= 1.f / (1.f + expf(-v1));
                } else if (ACT == 2) {
                    v0 = 1.f / (1.f + expf(-v0));
                    v1 = 1.f / (1.f + expf(-v1));
                }
                if (SPLIT_OUT) {
                    __half h0 = __float2half_rn(v0);
                    __half h1 = __float2half_rn(v1);
                    __half l0 = __float2half_rn(v0 - __half2float(h0));
                    __half l1 = __float2half_rn(v1 - __half2float(h1));
                    uint32_t hp = (uint32_t)__half_as_ushort(h0) | ((uint32_t)__half_as_ushort(h1) << 16);
                    uint32_t lp = (uint32_t)__half_as_ushort(l0) | ((uint32_t)__half_as_ushort(l1) << 16);
                    *(uint32_t*)&Chi[(size_t)m * N + n0] = hp;
                    *(uint32_t*)&Clo[(size_t)m * N + n0] = lp;
                } else {
                    *(float2*)&Cf[(size_t)m * N + n0] = make_float2(v0, v1);
                }
            }
        }
    }
}

// ---------------- weight transpose: W[K,N] fp32 -> T[N,K] fp16 -------------
__global__ __launch_bounds__(256)
void transpose_h(const float* __restrict__ W, __half* __restrict__ T, int K, int N)
{
    __shared__ float t[32][33];
    const int n0 = blockIdx.x * 32, k0 = blockIdx.y * 32;
    const int tx = threadIdx.x & 31, ty0 = threadIdx.x >> 5;
    #pragma unroll
    for (int dy = 0; dy < 32; dy += 8)
        t[ty0 + dy][tx] = W[(size_t)(k0 + ty0 + dy) * N + n0 + tx];
    __syncthreads();
    #pragma unroll
    for (int dy = 0; dy < 32; dy += 8) {
        int ty = ty0 + dy;
        T[(size_t)(n0 + ty) * K + k0 + tx] = __float2half_rn(t[tx][ty]);
    }
}

// ---------------- x split: [M,K] fp32 -> fp16 hi/lo ----------------
__global__ __launch_bounds__(256)
void split_only(const float* __restrict__ x, __half* __restrict__ hi,
                __half* __restrict__ lo, int n)
{
    int i = blockIdx.x * blockDim.x + threadIdx.x;
    if (i < n) {
        float v = x[i];
        __half h = __float2half_rn(v);
        hi[i] = h;
        lo[i] = __float2half_rn(v - __half2float(h));
    }
}

// ---------------- scan (minGRU linear recurrence), 3-pass chunked ----------------
__global__ __launch_bounds__(256)
void scan_pass1(const float* __restrict__ z, const float* __restrict__ ht,
                float* __restrict__ aggA, float* __restrict__ aggB)
{
    int t = blockIdx.x * blockDim.x + threadIdx.x;
    int f = t % EXPD, rc = t / EXPD, c = rc % NCH, bb = rc / NCH;
    size_t base = ((size_t)bb * SEQ + (size_t)c * CHL) * EXPD + f;
    float A = 1.f, B = 0.f;
    #pragma unroll 4
    for (int i = 0; i < CHL; i++) {
        size_t idx = base + (size_t)i * EXPD;
        float zi = z[idx], hi = ht[idx];
        float ai = 1.f - zi, bi = zi * hi;
        A = A * ai;
        B = B * ai + bi;
    }
    aggA[t] = A; aggB[t] = B;
}

__global__ __launch_bounds__(256)
void scan_pass2(const float* __restrict__ aggA, const float* __restrict__ aggB,
                float* __restrict__ carry)
{
    int t = blockIdx.x * blockDim.x + threadIdx.x;
    int f = t % EXPD, bb = t / EXPD;
    size_t base = (size_t)bb * NCH * EXPD + f;
    float h = 0.f;
    for (int c = 0; c < NCH; c++) {
        size_t idx = base + (size_t)c * EXPD;
        carry[idx] = h;
        h = aggA[idx] * h + aggB[idx];
    }
}

__global__ __launch_bounds__(256)
void scan_pass3(const float* __restrict__ z, const float* __restrict__ ht,
                const float* __restrict__ carry, const float* __restrict__ xskip,
                __half* __restrict__ uhi, __half* __restrict__ ulo)
{
    int t = blockIdx.x * blockDim.x + threadIdx.x;
    int f = t % EXPD, rc = t / EXPD, c = rc % NCH, bb = rc / NCH;
    size_t base = ((size_t)bb * SEQ + (size_t)c * CHL) * EXPD + f;
    float h = carry[t];
    #pragma unroll 4
    for (int i = 0; i < CHL; i++) {
        size_t idx = base + (size_t)i * EXPD;
        float zi = z[idx], hti = ht[idx];
        h = (1.f - zi) * h + zi * hti;
        float u = xskip[idx] + h;
        __half uh = __float2half_rn(u);
        uhi[idx] = uh;
        ulo[idx] = __float2half_rn(u - __half2float(uh));
    }
}

// ---------------- launch ----------------
extern "C" void kernel_launch(void* const* d_in, const int* in_sizes, int n_in,
                              void* d_out, int out_size)
{
    const float* x     = (const float*)d_in[0];
    const float* W_in1 = (const float*)d_in[1];
    const float* b_in1 = (const float*)d_in[2];
    const float* W_in2 = (const float*)d_in[3];
    const float* b_in2 = (const float*)d_in[4];
    const float* W_z   = (const float*)d_in[5];
    const float* b_z   = (const float*)d_in[6];
    const float* W_h   = (const float*)d_in[7];
    const float* b_h   = (const float*)d_in[8];
    const float* W_out = (const float*)d_in[9];
    const float* b_out = (const float*)d_in[10];
    float* out = (float*)d_out;

    __half *xhi, *xlo, *w1h, *w2h, *wzh, *whh, *woh, *xinhi, *xinlo, *uhi, *ulo;
    float *z, *ht, *xskip, *aggA, *aggB, *carry;
    cudaGetSymbolAddress((void**)&xhi, g_xhi);   cudaGetSymbolAddress((void**)&xlo, g_xlo);
    cudaGetSymbolAddress((void**)&w1h, g_w1h);   cudaGetSymbolAddress((void**)&w2h, g_w2h);
    cudaGetSymbolAddress((void**)&wzh, g_wzh);   cudaGetSymbolAddress((void**)&whh, g_whh);
    cudaGetSymbolAddress((void**)&woh, g_woh);
    cudaGetSymbolAddress((void**)&xinhi, g_xinhi); cudaGetSymbolAddress((void**)&xinlo, g_xinlo);
    cudaGetSymbolAddress((void**)&uhi, g_uhi);   cudaGetSymbolAddress((void**)&ulo, g_ulo);
    cudaGetSymbolAddress((void**)&z, g_z);       cudaGetSymbolAddress((void**)&ht, g_ht);
    cudaGetSymbolAddress((void**)&xskip, g_xskip);
    cudaGetSymbolAddress((void**)&aggA, g_aggA); cudaGetSymbolAddress((void**)&aggB, g_aggB);
    cudaGetSymbolAddress((void**)&carry, g_carry);

    cudaFuncSetAttribute(gemm_mma<1,1>, cudaFuncAttributeMaxDynamicSharedMemorySize, SMEM_BYTES);
    cudaFuncSetAttribute(gemm_mma<1,0>, cudaFuncAttributeMaxDynamicSharedMemorySize, SMEM_BYTES);
    cudaFuncSetAttribute(gemm_mma<2,0>, cudaFuncAttributeMaxDynamicSharedMemorySize, SMEM_BYTES);
    cudaFuncSetAttribute(gemm_mma<0,0>, cudaFuncAttributeMaxDynamicSharedMemorySize, SMEM_BYTES);

    // Launch order keeps a big GEMM at ncu's sampled launch index.
    // 0: split x
    split_only<<<(M_TOT * HID + 255) / 256, 256>>>(x, xhi, xlo, M_TOT * HID);
    // 1: W_in1^T
    transpose_h<<<dim3(EXPD/32, HID/32),  256>>>(W_in1, w1h, HID,  EXPD);
    // 2: W_z^T
    transpose_h<<<dim3(EXPD/32, EXPD/32), 256>>>(W_z,   wzh, EXPD, EXPD);
    // 3: x_in = silu(x@W_in1 + b1) -> fp16 split
    gemm_mma<1,1><<<dim3(EXPD/BN, M_TOT/BM), NTHREADS, SMEM_BYTES>>>(
        xhi, xlo, w1h, b_in1, nullptr, xinhi, xinlo, M_TOT, EXPD, HID);
    // 4: W_h^T
    transpose_h<<<dim3(EXPD/32, EXPD/32), 256>>>(W_h,   whh, EXPD, EXPD);
    // 5: z = sigmoid(x_in@W_z + bz)   <-- ncu samples near here
    gemm_mma<2,0><<<dim3(EXPD/BN, M_TOT/BM), NTHREADS, SMEM_BYTES>>>(
        xinhi, xinlo, wzh, b_z, z, nullptr, nullptr, M_TOT, EXPD, EXPD);
    // 6: W_in2^T
    transpose_h<<<dim3(EXPD/32, HID/32),  256>>>(W_in2, w2h, HID,  EXPD);
    // 7: x_skip = silu(x@W_in2 + b2) -> fp32
    gemm_mma<1,0><<<dim3(EXPD/BN, M_TOT/BM), NTHREADS, SMEM_BYTES>>>(
        xhi, xlo, w2h, b_in2, xskip, nullptr, nullptr, M_TOT, EXPD, HID);
    // 8: ht = x_in@W_h + bh
    gemm_mma<0,0><<<dim3(EXPD/BN, M_TOT/BM), NTHREADS, SMEM_BYTES>>>(
        xinhi, xinlo, whh, b_h, ht, nullptr, nullptr, M_TOT, EXPD, EXPD);
    // 9: W_out^T
    transpose_h<<<dim3(HID/32,  EXPD/32), 256>>>(W_out, woh, EXPD, HID);

    // 10-12: minGRU scan; pass3 fuses u = x_skip + h -> fp16 split
    int p1 = BATCH * NCH * EXPD;
    scan_pass1<<<p1 / 256, 256>>>(z, ht, aggA, aggB);
    scan_pass2<<<(BATCH * EXPD) / 256, 256>>>(aggA, aggB, carry);
    scan_pass3<<<p1 / 256, 256>>>(z, ht, carry, xskip, uhi, ulo);

    // 13: out = u @ W_out + b_out
    gemm_mma<0,0><<<dim3(HID/BN, M_TOT/BM), NTHREADS, SMEM_BYTES>>>(
        uhi, ulo, woh, b_out, out, nullptr, nullptr, M_TOT, HID, EXPD);
}

// round 9
// speedup vs baseline: 5.8032x; 1.3736x over previous
#include <cuda_runtime.h>
#include <cuda_fp16.h>
#include <cstdint>
#include <math.h>

// ---------------- problem dims (fixed) ----------------
#define HID   512
#define EXPD  2048
#define BATCH 4
#define SEQ   4096
#define M_TOT (BATCH*SEQ)      // 16384
#define NCH 64
#define CHL 64

// ---------------- scratch (device globals; 16B aligned) ----------------
__device__ __align__(16) __half g_xhi [(size_t)M_TOT*HID];
__device__ __align__(16) __half g_xlo [(size_t)M_TOT*HID];
__device__ __align__(16) __half g_w1h [(size_t)EXPD*HID];
__device__ __align__(16) __half g_w2h [(size_t)EXPD*HID];
__device__ __align__(16) __half g_wzh [(size_t)EXPD*EXPD];
__device__ __align__(16) __half g_whh [(size_t)EXPD*EXPD];
__device__ __align__(16) __half g_woh [(size_t)HID*EXPD];
__device__ __align__(16) __half g_xinhi[(size_t)M_TOT*EXPD];
__device__ __align__(16) __half g_xinlo[(size_t)M_TOT*EXPD];
__device__ __align__(16) float g_z    [(size_t)M_TOT*EXPD];
__device__ __align__(16) float g_ht   [(size_t)M_TOT*EXPD];
__device__ __align__(16) float g_xskip[(size_t)M_TOT*EXPD];
__device__ __align__(16) __half g_uhi[(size_t)M_TOT*EXPD];
__device__ __align__(16) __half g_ulo[(size_t)M_TOT*EXPD];
__device__ __align__(16) float g_aggA [(size_t)BATCH*NCH*EXPD];
__device__ __align__(16) float g_aggB [(size_t)BATCH*NCH*EXPD];
__device__ __align__(16) float g_carry[(size_t)BATCH*NCH*EXPD];

// ---------------- PTX helpers (base-target features only) ----------------
__device__ __forceinline__ uint32_t smem_u32(const void* p) {
    uint32_t a;
    asm("{ .reg .u64 t; cvta.to.shared.u64 t, %1; cvt.u32.u64 %0, t; }" : "=r"(a) : "l"(p));
    return a;
}
__device__ __forceinline__ void cp16(uint32_t dst, const void* src) {
    asm volatile("cp.async.cg.shared.global [%0], [%1], 16;" :: "r"(dst), "l"(src));
}
#define CP_COMMIT() asm volatile("cp.async.commit_group;" ::: "memory")
#define CP_WAIT(n)  asm volatile("cp.async.wait_group %0;" :: "n"(n) : "memory")

__device__ __forceinline__ void ldsm4(uint32_t* r, uint32_t addr) {
    asm volatile("ldmatrix.sync.aligned.m8n8.x4.shared.b16 {%0,%1,%2,%3}, [%4];"
        : "=r"(r[0]), "=r"(r[1]), "=r"(r[2]), "=r"(r[3]) : "r"(addr));
}
__device__ __forceinline__ void mma_f16(float* c, const uint32_t* a, const uint32_t* b) {
    asm volatile(
        "mma.sync.aligned.m16n8k16.row.col.f32.f16.f16.f32 "
        "{%0,%1,%2,%3}, {%4,%5,%6,%7}, {%8,%9}, {%0,%1,%2,%3};"
        : "+f"(c[0]), "+f"(c[1]), "+f"(c[2]), "+f"(c[3])
        : "r"(a[0]), "r"(a[1]), "r"(a[2]), "r"(a[3]), "r"(b[0]), "r"(b[1]));
}

// ---------------- mma.sync GEMM: C[M,N] = act((Ahi[+Alo])[M,K] @ (B[N,K])^T + bias) ------
// NTERMS=2: A split in fp16 (hi+lo, exact to 2^-22). NTERMS=1: A-hi only (~2.8e-4 extra).
// 512 threads: 16 warps, 4m x 4n, warp tile 32x64.
#define BM 128
#define BN 256
#define BK 64
#define NTHREADS 512
#define T_AHI 0
#define T_ALO 16384
#define T_B   32768
#define STAGE_BYTES 65536
#define NSTAGE 3
#define SMEM_BYTES (NSTAGE*STAGE_BYTES)

// ACT: 0=none 1=silu 2=sigmoid ; SPLIT_OUT: 0 -> Cf fp32 ; 1 -> Chi/Clo fp16
template<int ACT, int SPLIT_OUT, int NTERMS>
__global__ __launch_bounds__(NTHREADS, 1)
void gemm_mma(const __half* __restrict__ Ahi, const __half* __restrict__ Alo,
              const __half* __restrict__ B,
              const float* __restrict__ bias,
              float* __restrict__ Cf, __half* __restrict__ Chi, __half* __restrict__ Clo,
              int M, int N, int K)
{
    extern __shared__ char smem[];
    const uint32_t sb = smem_u32(smem);
    const int tid  = threadIdx.x;
    const int wid  = tid >> 5;
    const int lane = tid & 31;
    const int wm = wid >> 2;           // 0..3  -> m offset wm*32
    const int wn = wid & 3;            // 0..3  -> n offset wn*64
    const int bm = blockIdx.y * BM;
    const int bn = blockIdx.x * BN;

    const int Kv = K >> 3;             // row pitch in uint4 (8 fp16)
    const uint4* gAhi = (const uint4*)Ahi;
    const uint4* gAlo = (const uint4*)Alo;
    const uint4* gB   = (const uint4*)B;

    const int nk = K / BK;

    auto load_stage = [&](int buf, int kc) {
        const int kv0 = kc * (BK / 8);
        const uint32_t base = sb + buf * STAGE_BYTES;
        #pragma unroll
        for (int t = 0; t < 2; t++) {           // A: 128 rows x 8 chunks
            int i = tid + t * NTHREADS;
            int row = i >> 3, ch = i & 7;
            uint32_t so = (uint32_t)(row * 128 + ((ch ^ (row & 7)) << 4));
            size_t ga = (size_t)(bm + row) * Kv + kv0 + ch;
            cp16(base + T_AHI + so, gAhi + ga);
            if (NTERMS == 2) cp16(base + T_ALO + so, gAlo + ga);
        }
        #pragma unroll
        for (int t = 0; t < 4; t++) {           // B: 256 rows x 8 chunks
            int i = tid + t * NTHREADS;
            int row = i >> 3, ch = i & 7;
            uint32_t so = (uint32_t)(row * 128 + ((ch ^ (row & 7)) << 4));
            size_t gb = (size_t)(bn + row) * Kv + kv0 + ch;
            cp16(base + T_B + so, gB + gb);
        }
    };

    float acc[2][8][4];
    #pragma unroll
    for (int mi = 0; mi < 2; mi++)
        #pragma unroll
        for (int ni = 0; ni < 8; ni++)
            #pragma unroll
            for (int q = 0; q < 4; q++)
                acc[mi][ni][q] = 0.f;

    load_stage(0, 0);
    CP_COMMIT();
    load_stage(1, 1);
    CP_COMMIT();

    for (int kc = 0; kc < nk; kc++) {
        const int buf = kc % NSTAGE;
        if (kc + 1 < nk) { CP_WAIT(1); } else { CP_WAIT(0); }
        __syncthreads();
        if (kc + 2 < nk) {
            load_stage((kc + 2) % NSTAGE, kc + 2);
            CP_COMMIT();
        }

        const uint32_t st = sb + buf * STAGE_BYTES;
        #pragma unroll
        for (int kk = 0; kk < BK / 16; kk++) {
            const int byteCol = kk * 32 + ((lane >> 4) << 4);
            // A fragments: 2 m16 tiles (hi, and lo if NTERMS==2)
            uint32_t ah[2][4], al[2][4];
            #pragma unroll
            for (int mi = 0; mi < 2; mi++) {
                int row = wm * 32 + mi * 16 + (lane & 15);
                uint32_t so = (uint32_t)(row * 128 + byteCol) ^ ((uint32_t)(row & 7) << 4);
                ldsm4(ah[mi], st + T_AHI + so);
                if (NTERMS == 2) ldsm4(al[mi], st + T_ALO + so);
            }
            // B: 4 ldsm cover 64 n (8 n8-tiles)
            #pragma unroll
            for (int nt = 0; nt < 4; nt++) {
                int row = wn * 64 + nt * 16 + (lane & 15);
                uint32_t so = (uint32_t)(row * 128 + byteCol) ^ ((uint32_t)(row & 7) << 4);
                uint32_t rh[4];
                ldsm4(rh, st + T_B + so);
                uint32_t b0[2] = { rh[0], rh[2] }, b1[2] = { rh[1], rh[3] };
                #pragma unroll
                for (int mi = 0; mi < 2; mi++) {
                    mma_f16(acc[mi][2*nt+0], ah[mi], b0);
                    mma_f16(acc[mi][2*nt+1], ah[mi], b1);
                    if (NTERMS == 2) {
                        mma_f16(acc[mi][2*nt+0], al[mi], b0);
                        mma_f16(acc[mi][2*nt+1], al[mi], b1);
                    }
                }
            }
        }
    }

    // ---------------- epilogue: bias + activation + store ----------------
    const int qrow = lane >> 2;        // 0..7
    const int qcol = (lane & 3) * 2;   // 0,2,4,6
    #pragma unroll
    for (int mi = 0; mi < 2; mi++) {
        #pragma unroll
        for (int ni = 0; ni < 8; ni++) {
            const int n0 = bn + wn * 64 + ni * 8 + qcol;
            const float bias0 = bias[n0], bias1 = bias[n0 + 1];
            #pragma unroll
            for (int half_ = 0; half_ < 2; half_++) {
                const int m = bm + wm * 32 + mi * 16 + qrow + half_ * 8;
                float v0 = acc[mi][ni][half_ * 2 + 0] + bias0;
                float v1 = acc[mi][ni][half_ * 2 + 1] + bias1;
                if (ACT == 1) {
                    v0 *= 1.f / (1.f + expf(-v0));
                    v1 *= 1.f / (1.f + expf(-v1));
                } else if (ACT == 2) {
                    v0 = 1.f / (1.f + expf(-v0));
                    v1 = 1.f / (1.f + expf(-v1));
                }
                if (SPLIT_OUT) {
                    __half h0 = __float2half_rn(v0);
                    __half h1 = __float2half_rn(v1);
                    __half l0 = __float2half_rn(v0 - __half2float(h0));
                    __half l1 = __float2half_rn(v1 - __half2float(h1));
                    uint32_t hp = (uint32_t)__half_as_ushort(h0) | ((uint32_t)__half_as_ushort(h1) << 16);
                    uint32_t lp = (uint32_t)__half_as_ushort(l0) | ((uint32_t)__half_as_ushort(l1) << 16);
                    *(uint32_t*)&Chi[(size_t)m * N + n0] = hp;
                    *(uint32_t*)&Clo[(size_t)m * N + n0] = lp;
                } else {
                    *(float2*)&Cf[(size_t)m * N + n0] = make_float2(v0, v1);
                }
            }
        }
    }
}

// ---------------- weight transpose: W[K,N] fp32 -> T[N,K] fp16 -------------
__global__ __launch_bounds__(256)
void transpose_h(const float* __restrict__ W, __half* __restrict__ T, int K, int N)
{
    __shared__ float t[32][33];
    const int n0 = blockIdx.x * 32, k0 = blockIdx.y * 32;
    const int tx = threadIdx.x & 31, ty0 = threadIdx.x >> 5;
    #pragma unroll
    for (int dy = 0; dy < 32; dy += 8)
        t[ty0 + dy][tx] = W[(size_t)(k0 + ty0 + dy) * N + n0 + tx];
    __syncthreads();
    #pragma unroll
    for (int dy = 0; dy < 32; dy += 8) {
        int ty = ty0 + dy;
        T[(size_t)(n0 + ty) * K + k0 + tx] = __float2half_rn(t[tx][ty]);
    }
}

// ---------------- x split: [M,K] fp32 -> fp16 hi/lo ----------------
__global__ __launch_bounds__(256)
void split_only(const float* __restrict__ x, __half* __restrict__ hi,
                __half* __restrict__ lo, int n)
{
    int i = blockIdx.x * blockDim.x + threadIdx.x;
    if (i < n) {
        float v = x[i];
        __half h = __float2half_rn(v);
        hi[i] = h;
        lo[i] = __float2half_rn(v - __half2float(h));
    }
}

// ---------------- scan (minGRU linear recurrence), 3-pass chunked ----------------
__global__ __launch_bounds__(256)
void scan_pass1(const float* __restrict__ z, const float* __restrict__ ht,
                float* __restrict__ aggA, float* __restrict__ aggB)
{
    int t = blockIdx.x * blockDim.x + threadIdx.x;
    int f = t % EXPD, rc = t / EXPD, c = rc % NCH, bb = rc / NCH;
    size_t base = ((size_t)bb * SEQ + (size_t)c * CHL) * EXPD + f;
    float A = 1.f, B = 0.f;
    #pragma unroll 4
    for (int i = 0; i < CHL; i++) {
        size_t idx = base + (size_t)i * EXPD;
        float zi = z[idx], hi = ht[idx];
        float ai = 1.f - zi, bi = zi * hi;
        A = A * ai;
        B = B * ai + bi;
    }
    aggA[t] = A; aggB[t] = B;
}

__global__ __launch_bounds__(256)
void scan_pass2(const float* __restrict__ aggA, const float* __restrict__ aggB,
                float* __restrict__ carry)
{
    int t = blockIdx.x * blockDim.x + threadIdx.x;
    int f = t % EXPD, bb = t / EXPD;
    size_t base = (size_t)bb * NCH * EXPD + f;
    float h = 0.f;
    for (int c = 0; c < NCH; c++) {
        size_t idx = base + (size_t)c * EXPD;
        carry[idx] = h;
        h = aggA[idx] * h + aggB[idx];
    }
}

__global__ __launch_bounds__(256)
void scan_pass3(const float* __restrict__ z, const float* __restrict__ ht,
                const float* __restrict__ carry, const float* __restrict__ xskip,
                __half* __restrict__ uhi, __half* __restrict__ ulo)
{
    int t = blockIdx.x * blockDim.x + threadIdx.x;
    int f = t % EXPD, rc = t / EXPD, c = rc % NCH, bb = rc / NCH;
    size_t base = ((size_t)bb * SEQ + (size_t)c * CHL) * EXPD + f;
    float h = carry[t];
    #pragma unroll 4
    for (int i = 0; i < CHL; i++) {
        size_t idx = base + (size_t)i * EXPD;
        float zi = z[idx], hti = ht[idx];
        h = (1.f - zi) * h + zi * hti;
        float u = xskip[idx] + h;
        __half uh = __float2half_rn(u);
        uhi[idx] = uh;
        ulo[idx] = __float2half_rn(u - __half2float(uh));
    }
}

// ---------------- launch ----------------
extern "C" void kernel_launch(void* const* d_in, const int* in_sizes, int n_in,
                              void* d_out, int out_size)
{
    const float* x     = (const float*)d_in[0];
    const float* W_in1 = (const float*)d_in[1];
    const float* b_in1 = (const float*)d_in[2];
    const float* W_in2 = (const float*)d_in[3];
    const float* b_in2 = (const float*)d_in[4];
    const float* W_z   = (const float*)d_in[5];
    const float* b_z   = (const float*)d_in[6];
    const float* W_h   = (const float*)d_in[7];
    const float* b_h   = (const float*)d_in[8];
    const float* W_out = (const float*)d_in[9];
    const float* b_out = (const float*)d_in[10];
    float* out = (float*)d_out;

    __half *xhi, *xlo, *w1h, *w2h, *wzh, *whh, *woh, *xinhi, *xinlo, *uhi, *ulo;
    float *z, *ht, *xskip, *aggA, *aggB, *carry;
    cudaGetSymbolAddress((void**)&xhi, g_xhi);   cudaGetSymbolAddress((void**)&xlo, g_xlo);
    cudaGetSymbolAddress((void**)&w1h, g_w1h);   cudaGetSymbolAddress((void**)&w2h, g_w2h);
    cudaGetSymbolAddress((void**)&wzh, g_wzh);   cudaGetSymbolAddress((void**)&whh, g_whh);
    cudaGetSymbolAddress((void**)&woh, g_woh);
    cudaGetSymbolAddress((void**)&xinhi, g_xinhi); cudaGetSymbolAddress((void**)&xinlo, g_xinlo);
    cudaGetSymbolAddress((void**)&uhi, g_uhi);   cudaGetSymbolAddress((void**)&ulo, g_ulo);
    cudaGetSymbolAddress((void**)&z, g_z);       cudaGetSymbolAddress((void**)&ht, g_ht);
    cudaGetSymbolAddress((void**)&xskip, g_xskip);
    cudaGetSymbolAddress((void**)&aggA, g_aggA); cudaGetSymbolAddress((void**)&aggB, g_aggB);
    cudaGetSymbolAddress((void**)&carry, g_carry);

    cudaFuncSetAttribute(gemm_mma<1,1,2>, cudaFuncAttributeMaxDynamicSharedMemorySize, SMEM_BYTES);
    cudaFuncSetAttribute(gemm_mma<1,0,2>, cudaFuncAttributeMaxDynamicSharedMemorySize, SMEM_BYTES);
    cudaFuncSetAttribute(gemm_mma<2,0,1>, cudaFuncAttributeMaxDynamicSharedMemorySize, SMEM_BYTES);
    cudaFuncSetAttribute(gemm_mma<0,0,1>, cudaFuncAttributeMaxDynamicSharedMemorySize, SMEM_BYTES);
    cudaFuncSetAttribute(gemm_mma<0,0,2>, cudaFuncAttributeMaxDynamicSharedMemorySize, SMEM_BYTES);

    // 0: split x
    split_only<<<(M_TOT * HID + 255) / 256, 256>>>(x, xhi, xlo, M_TOT * HID);
    // 1: W_in1^T
    transpose_h<<<dim3(EXPD/32, HID/32),  256>>>(W_in1, w1h, HID,  EXPD);
    // 2: W_z^T
    transpose_h<<<dim3(EXPD/32, EXPD/32), 256>>>(W_z,   wzh, EXPD, EXPD);
    // 3: x_in = silu(x@W_in1 + b1) -> fp16 split  (2-term A)
    gemm_mma<1,1,2><<<dim3(EXPD/BN, M_TOT/BM), NTHREADS, SMEM_BYTES>>>(
        xhi, xlo, w1h, b_in1, nullptr, xinhi, xinlo, M_TOT, EXPD, HID);
    // 4: W_h^T
    transpose_h<<<dim3(EXPD/32, EXPD/32), 256>>>(W_h,   whh, EXPD, EXPD);
    // 5: z = sigmoid(x_in@W_z + bz)  (1-term A)  <-- ncu samples near here
    gemm_mma<2,0,1><<<dim3(EXPD/BN, M_TOT/BM), NTHREADS, SMEM_BYTES>>>(
        xinhi, xinlo, wzh, b_z, z, nullptr, nullptr, M_TOT, EXPD, EXPD);
    // 6: W_in2^T
    transpose_h<<<dim3(EXPD/32, HID/32),  256>>>(W_in2, w2h, HID,  EXPD);
    // 7: x_skip = silu(x@W_in2 + b2) -> fp32  (2-term A)
    gemm_mma<1,0,2><<<dim3(EXPD/BN, M_TOT/BM), NTHREADS, SMEM_BYTES>>>(
        xhi, xlo, w2h, b_in2, xskip, nullptr, nullptr, M_TOT, EXPD, HID);
    // 8: ht = x_in@W_h + bh  (1-term A)
    gemm_mma<0,0,1><<<dim3(EXPD/BN, M_TOT/BM), NTHREADS, SMEM_BYTES>>>(
        xinhi, xinlo, whh, b_h, ht, nullptr, nullptr, M_TOT, EXPD, EXPD);
    // 9: W_out^T
    transpose_h<<<dim3(HID/32,  EXPD/32), 256>>>(W_out, woh, EXPD, HID);

    // 10-12: minGRU scan; pass3 fuses u = x_skip + h -> fp16 split
    int p1 = BATCH * NCH * EXPD;
    scan_pass1<<<p1 / 256, 256>>>(z, ht, aggA, aggB);
    scan_pass2<<<(BATCH * EXPD) / 256, 256>>>(aggA, aggB, carry);
    scan_pass3<<<p1 / 256, 256>>>(z, ht, carry, xskip, uhi, ulo);

    // 13: out = u @ W_out + b_out  (2-term A)
    gemm_mma<0,0,2><<<dim3(HID/BN, M_TOT/BM), NTHREADS, SMEM_BYTES>>>(
        uhi, ulo, woh, b_out, out, nullptr, nullptr, M_TOT, HID, EXPD);
}

// round 10
// speedup vs baseline: 7.0877x; 1.2213x over previous
#include <cuda_runtime.h>
#include <cuda_fp16.h>
#include <cstdint>
#include <math.h>

// ---------------- problem dims (fixed) ----------------
#define HID   512
#define EXPD  2048
#define BATCH 4
#define SEQ   4096
#define M_TOT (BATCH*SEQ)      // 16384
#define NCH 64
#define CHL 64

// ---------------- scratch (device globals; 16B aligned) ----------------
__device__ __align__(16) __half g_xh  [(size_t)M_TOT*HID];
__device__ __align__(16) __half g_w1h [(size_t)EXPD*HID];
__device__ __align__(16) __half g_w2h [(size_t)EXPD*HID];
__device__ __align__(16) __half g_wzh [(size_t)EXPD*EXPD];
__device__ __align__(16) __half g_whh [(size_t)EXPD*EXPD];
__device__ __align__(16) __half g_woh [(size_t)HID*EXPD];
__device__ __align__(16) __half g_xin [(size_t)M_TOT*EXPD];
__device__ __align__(16) __half g_z   [(size_t)M_TOT*EXPD];
__device__ __align__(16) __half g_ht  [(size_t)M_TOT*EXPD];
__device__ __align__(16) float g_xskip[(size_t)M_TOT*EXPD];
__device__ __align__(16) __half g_u   [(size_t)M_TOT*EXPD];
__device__ __align__(16) float g_aggA [(size_t)BATCH*NCH*EXPD];
__device__ __align__(16) float g_aggB [(size_t)BATCH*NCH*EXPD];
__device__ __align__(16) float g_carry[(size_t)BATCH*NCH*EXPD];

// ---------------- PTX helpers (base-target features only) ----------------
__device__ __forceinline__ uint32_t smem_u32(const void* p) {
    uint32_t a;
    asm("{ .reg .u64 t; cvta.to.shared.u64 t, %1; cvt.u32.u64 %0, t; }" : "=r"(a) : "l"(p));
    return a;
}
__device__ __forceinline__ void cp16(uint32_t dst, const void* src) {
    asm volatile("cp.async.cg.shared.global [%0], [%1], 16;" :: "r"(dst), "l"(src));
}
#define CP_COMMIT() asm volatile("cp.async.commit_group;" ::: "memory")
#define CP_WAIT(n)  asm volatile("cp.async.wait_group %0;" :: "n"(n) : "memory")

__device__ __forceinline__ void ldsm4(uint32_t* r, uint32_t addr) {
    asm volatile("ldmatrix.sync.aligned.m8n8.x4.shared.b16 {%0,%1,%2,%3}, [%4];"
        : "=r"(r[0]), "=r"(r[1]), "=r"(r[2]), "=r"(r[3]) : "r"(addr));
}
__device__ __forceinline__ void mma_f16(float* c, const uint32_t* a, const uint32_t* b) {
    asm volatile(
        "mma.sync.aligned.m16n8k16.row.col.f32.f16.f16.f32 "
        "{%0,%1,%2,%3}, {%4,%5,%6,%7}, {%8,%9}, {%0,%1,%2,%3};"
        : "+f"(c[0]), "+f"(c[1]), "+f"(c[2]), "+f"(c[3])
        : "r"(a[0]), "r"(a[1]), "r"(a[2]), "r"(a[3]), "r"(b[0]), "r"(b[1]));
}

// ---------------- mma.sync GEMM: C[M,N] = act(A[M,K] @ (B[N,K])^T + bias) ------
// A, B fp16 (single term). 512 threads: 16 warps, 4m x 4n, warp tile 32x64.
#define BM 128
#define BN 256
#define BK 64
#define NTHREADS 512
#define T_A 0
#define T_B 16384
#define STAGE_BYTES 49152
#define NSTAGE 3
#define SMEM_BYTES (NSTAGE*STAGE_BYTES)

// ACT: 0=none 1=silu 2=sigmoid ; OUT: 0 -> Cf fp32 ; 1 -> Ch fp16
template<int ACT, int OUT>
__global__ __launch_bounds__(NTHREADS, 1)
void gemm_mma(const __half* __restrict__ A, const __half* __restrict__ B,
              const float* __restrict__ bias,
              float* __restrict__ Cf, __half* __restrict__ Ch,
              int M, int N, int K)
{
    extern __shared__ char smem[];
    const uint32_t sb = smem_u32(smem);
    const int tid  = threadIdx.x;
    const int wid  = tid >> 5;
    const int lane = tid & 31;
    const int wm = wid >> 2;           // 0..3  -> m offset wm*32
    const int wn = wid & 3;            // 0..3  -> n offset wn*64
    const int bm = blockIdx.y * BM;
    const int bn = blockIdx.x * BN;

    const int Kv = K >> 3;             // row pitch in uint4 (8 fp16)
    const uint4* gA = (const uint4*)A;
    const uint4* gB = (const uint4*)B;

    const int nk = K / BK;

    auto load_stage = [&](int buf, int kc) {
        const int kv0 = kc * (BK / 8);
        const uint32_t base = sb + buf * STAGE_BYTES;
        #pragma unroll
        for (int t = 0; t < 2; t++) {           // A: 128 rows x 8 chunks
            int i = tid + t * NTHREADS;
            int row = i >> 3, ch = i & 7;
            uint32_t so = (uint32_t)(row * 128 + ((ch ^ (row & 7)) << 4));
            cp16(base + T_A + so, gA + (size_t)(bm + row) * Kv + kv0 + ch);
        }
        #pragma unroll
        for (int t = 0; t < 4; t++) {           // B: 256 rows x 8 chunks
            int i = tid + t * NTHREADS;
            int row = i >> 3, ch = i & 7;
            uint32_t so = (uint32_t)(row * 128 + ((ch ^ (row & 7)) << 4));
            cp16(base + T_B + so, gB + (size_t)(bn + row) * Kv + kv0 + ch);
        }
    };

    float acc[2][8][4];
    #pragma unroll
    for (int mi = 0; mi < 2; mi++)
        #pragma unroll
        for (int ni = 0; ni < 8; ni++)
            #pragma unroll
            for (int q = 0; q < 4; q++)
                acc[mi][ni][q] = 0.f;

    load_stage(0, 0);
    CP_COMMIT();
    load_stage(1, 1);
    CP_COMMIT();

    for (int kc = 0; kc < nk; kc++) {
        const int buf = kc % NSTAGE;
        if (kc + 1 < nk) { CP_WAIT(1); } else { CP_WAIT(0); }
        __syncthreads();
        if (kc + 2 < nk) {
            load_stage((kc + 2) % NSTAGE, kc + 2);
            CP_COMMIT();
        }

        const uint32_t st = sb + buf * STAGE_BYTES;
        #pragma unroll
        for (int kk = 0; kk < BK / 16; kk++) {
            const int byteCol = kk * 32 + ((lane >> 4) << 4);
            uint32_t ah[2][4];
            #pragma unroll
            for (int mi = 0; mi < 2; mi++) {
                int row = wm * 32 + mi * 16 + (lane & 15);
                uint32_t so = (uint32_t)(row * 128 + byteCol) ^ ((uint32_t)(row & 7) << 4);
                ldsm4(ah[mi], st + T_A + so);
            }
            #pragma unroll
            for (int nt = 0; nt < 4; nt++) {
                int row = wn * 64 + nt * 16 + (lane & 15);
                uint32_t so = (uint32_t)(row * 128 + byteCol) ^ ((uint32_t)(row & 7) << 4);
                uint32_t rh[4];
                ldsm4(rh, st + T_B + so);
                uint32_t b0[2] = { rh[0], rh[2] }, b1[2] = { rh[1], rh[3] };
                #pragma unroll
                for (int mi = 0; mi < 2; mi++) {
                    mma_f16(acc[mi][2*nt+0], ah[mi], b0);
                    mma_f16(acc[mi][2*nt+1], ah[mi], b1);
                }
            }
        }
    }

    // ---------------- epilogue: bias + activation + store ----------------
    const int qrow = lane >> 2;        // 0..7
    const int qcol = (lane & 3) * 2;   // 0,2,4,6
    #pragma unroll
    for (int mi = 0; mi < 2; mi++) {
        #pragma unroll
        for (int ni = 0; ni < 8; ni++) {
            const int n0 = bn + wn * 64 + ni * 8 + qcol;
            const float bias0 = bias[n0], bias1 = bias[n0 + 1];
            #pragma unroll
            for (int half_ = 0; half_ < 2; half_++) {
                const int m = bm + wm * 32 + mi * 16 + qrow + half_ * 8;
                float v0 = acc[mi][ni][half_ * 2 + 0] + bias0;
                float v1 = acc[mi][ni][half_ * 2 + 1] + bias1;
                if (ACT == 1) {
                    v0 *= 1.f / (1.f + expf(-v0));
                    v1 *= 1.f / (1.f + expf(-v1));
                } else if (ACT == 2) {
                    v0 = 1.f / (1.f + expf(-v0));
                    v1 = 1.f / (1.f + expf(-v1));
                }
                if (OUT == 1) {
                    __half h0 = __float2half_rn(v0);
                    __half h1 = __float2half_rn(v1);
                    uint32_t hp = (uint32_t)__half_as_ushort(h0) | ((uint32_t)__half_as_ushort(h1) << 16);
                    *(uint32_t*)&Ch[(size_t)m * N + n0] = hp;
                } else {
                    *(float2*)&Cf[(size_t)m * N + n0] = make_float2(v0, v1);
                }
            }
        }
    }
}

// ---------------- weight transpose: W[K,N] fp32 -> T[N,K] fp16 -------------
__global__ __launch_bounds__(256)
void transpose_h(const float* __restrict__ W, __half* __restrict__ T, int K, int N)
{
    __shared__ float t[32][33];
    const int n0 = blockIdx.x * 32, k0 = blockIdx.y * 32;
    const int tx = threadIdx.x & 31, ty0 = threadIdx.x >> 5;
    #pragma unroll
    for (int dy = 0; dy < 32; dy += 8)
        t[ty0 + dy][tx] = W[(size_t)(k0 + ty0 + dy) * N + n0 + tx];
    __syncthreads();
    #pragma unroll
    for (int dy = 0; dy < 32; dy += 8) {
        int ty = ty0 + dy;
        T[(size_t)(n0 + ty) * K + k0 + tx] = __float2half_rn(t[tx][ty]);
    }
}

// ---------------- x convert: fp32 -> fp16 ----------------
__global__ __launch_bounds__(256)
void convert_h(const float* __restrict__ x, __half* __restrict__ h, int n)
{
    int i = blockIdx.x * blockDim.x + threadIdx.x;
    if (i < n) h[i] = __float2half_rn(x[i]);
}

// ---------------- scan (minGRU linear recurrence), 3-pass chunked ----------------
__global__ __launch_bounds__(256)
void scan_pass1(const __half* __restrict__ z, const __half* __restrict__ ht,
                float* __restrict__ aggA, float* __restrict__ aggB)
{
    int t = blockIdx.x * blockDim.x + threadIdx.x;
    int f = t % EXPD, rc = t / EXPD, c = rc % NCH, bb = rc / NCH;
    size_t base = ((size_t)bb * SEQ + (size_t)c * CHL) * EXPD + f;
    float A = 1.f, B = 0.f;
    #pragma unroll 4
    for (int i = 0; i < CHL; i++) {
        size_t idx = base + (size_t)i * EXPD;
        float zi = __half2float(z[idx]), hi = __half2float(ht[idx]);
        float ai = 1.f - zi, bi = zi * hi;
        A = A * ai;
        B = B * ai + bi;
    }
    aggA[t] = A; aggB[t] = B;
}

__global__ __launch_bounds__(256)
void scan_pass2(const float* __restrict__ aggA, const float* __restrict__ aggB,
                float* __restrict__ carry)
{
    int t = blockIdx.x * blockDim.x + threadIdx.x;
    int f = t % EXPD, bb = t / EXPD;
    size_t base = (size_t)bb * NCH * EXPD + f;
    float h = 0.f;
    for (int c = 0; c < NCH; c++) {
        size_t idx = base + (size_t)c * EXPD;
        carry[idx] = h;
        h = aggA[idx] * h + aggB[idx];
    }
}

__global__ __launch_bounds__(256)
void scan_pass3(const __half* __restrict__ z, const __half* __restrict__ ht,
                const float* __restrict__ carry, const float* __restrict__ xskip,
                __half* __restrict__ u)
{
    int t = blockIdx.x * blockDim.x + threadIdx.x;
    int f = t % EXPD, rc = t / EXPD, c = rc % NCH, bb = rc / NCH;
    size_t base = ((size_t)bb * SEQ + (size_t)c * CHL) * EXPD + f;
    float h = carry[t];
    #pragma unroll 4
    for (int i = 0; i < CHL; i++) {
        size_t idx = base + (size_t)i * EXPD;
        float zi = __half2float(z[idx]), hti = __half2float(ht[idx]);
        h = (1.f - zi) * h + zi * hti;
        u[idx] = __float2half_rn(xskip[idx] + h);
    }
}

// ---------------- launch ----------------
extern "C" void kernel_launch(void* const* d_in, const int* in_sizes, int n_in,
                              void* d_out, int out_size)
{
    const float* x     = (const float*)d_in[0];
    const float* W_in1 = (const float*)d_in[1];
    const float* b_in1 = (const float*)d_in[2];
    const float* W_in2 = (const float*)d_in[3];
    const float* b_in2 = (const float*)d_in[4];
    const float* W_z   = (const float*)d_in[5];
    const float* b_z   = (const float*)d_in[6];
    const float* W_h   = (const float*)d_in[7];
    const float* b_h   = (const float*)d_in[8];
    const float* W_out = (const float*)d_in[9];
    const float* b_out = (const float*)d_in[10];
    float* out = (float*)d_out;

    __half *xh, *w1h, *w2h, *wzh, *whh, *woh, *xin, *zh, *hth, *u;
    float *xskip, *aggA, *aggB, *carry;
    cudaGetSymbolAddress((void**)&xh, g_xh);
    cudaGetSymbolAddress((void**)&w1h, g_w1h);   cudaGetSymbolAddress((void**)&w2h, g_w2h);
    cudaGetSymbolAddress((void**)&wzh, g_wzh);   cudaGetSymbolAddress((void**)&whh, g_whh);
    cudaGetSymbolAddress((void**)&woh, g_woh);
    cudaGetSymbolAddress((void**)&xin, g_xin);
    cudaGetSymbolAddress((void**)&zh, g_z);      cudaGetSymbolAddress((void**)&hth, g_ht);
    cudaGetSymbolAddress((void**)&u, g_u);
    cudaGetSymbolAddress((void**)&xskip, g_xskip);
    cudaGetSymbolAddress((void**)&aggA, g_aggA); cudaGetSymbolAddress((void**)&aggB, g_aggB);
    cudaGetSymbolAddress((void**)&carry, g_carry);

    cudaFuncSetAttribute(gemm_mma<1,1>, cudaFuncAttributeMaxDynamicSharedMemorySize, SMEM_BYTES);
    cudaFuncSetAttribute(gemm_mma<1,0>, cudaFuncAttributeMaxDynamicSharedMemorySize, SMEM_BYTES);
    cudaFuncSetAttribute(gemm_mma<2,1>, cudaFuncAttributeMaxDynamicSharedMemorySize, SMEM_BYTES);
    cudaFuncSetAttribute(gemm_mma<0,1>, cudaFuncAttributeMaxDynamicSharedMemorySize, SMEM_BYTES);
    cudaFuncSetAttribute(gemm_mma<0,0>, cudaFuncAttributeMaxDynamicSharedMemorySize, SMEM_BYTES);

    // 0: convert x -> fp16
    convert_h<<<(M_TOT * HID + 255) / 256, 256>>>(x, xh, M_TOT * HID);
    // 1: W_in1^T
    transpose_h<<<dim3(EXPD/32, HID/32),  256>>>(W_in1, w1h, HID,  EXPD);
    // 2: W_z^T
    transpose_h<<<dim3(EXPD/32, EXPD/32), 256>>>(W_z,   wzh, EXPD, EXPD);
    // 3: x_in = silu(x@W_in1 + b1) -> fp16
    gemm_mma<1,1><<<dim3(EXPD/BN, M_TOT/BM), NTHREADS, SMEM_BYTES>>>(
        xh, w1h, b_in1, nullptr, xin, M_TOT, EXPD, HID);
    // 4: W_h^T
    transpose_h<<<dim3(EXPD/32, EXPD/32), 256>>>(W_h,   whh, EXPD, EXPD);
    // 5: z = sigmoid(x_in@W_z + bz) -> fp16   <-- ncu samples this launch
    gemm_mma<2,1><<<dim3(EXPD/BN, M_TOT/BM), NTHREADS, SMEM_BYTES>>>(
        xin, wzh, b_z, nullptr, zh, M_TOT, EXPD, EXPD);
    // 6: W_in2^T
    transpose_h<<<dim3(EXPD/32, HID/32),  256>>>(W_in2, w2h, HID,  EXPD);
    // 7: x_skip = silu(x@W_in2 + b2) -> fp32
    gemm_mma<1,0><<<dim3(EXPD/BN, M_TOT/BM), NTHREADS, SMEM_BYTES>>>(
        xh, w2h, b_in2, xskip, nullptr, M_TOT, EXPD, HID);
    // 8: ht = x_in@W_h + bh -> fp16
    gemm_mma<0,1><<<dim3(EXPD/BN, M_TOT/BM), NTHREADS, SMEM_BYTES>>>(
        xin, whh, b_h, nullptr, hth, M_TOT, EXPD, EXPD);
    // 9: W_out^T
    transpose_h<<<dim3(HID/32,  EXPD/32), 256>>>(W_out, woh, EXPD, HID);

    // 10-12: minGRU scan; pass3 fuses u = x_skip + h -> fp16
    int p1 = BATCH * NCH * EXPD;
    scan_pass1<<<p1 / 256, 256>>>(zh, hth, aggA, aggB);
    scan_pass2<<<(BATCH * EXPD) / 256, 256>>>(aggA, aggB, carry);
    scan_pass3<<<p1 / 256, 256>>>(zh, hth, carry, xskip, u);

    // 13: out = u @ W_out + b_out -> fp32
    gemm_mma<0,0><<<dim3(HID/BN, M_TOT/BM), NTHREADS, SMEM_BYTES>>>(
        u, woh, b_out, out, nullptr, M_TOT, HID, EXPD);
}

// round 11
// speedup vs baseline: 7.4992x; 1.0581x over previous
#include <cuda_runtime.h>
#include <cuda_fp16.h>
#include <cstdint>
#include <math.h>

// ---------------- problem dims (fixed) ----------------
#define HID   512
#define EXPD  2048
#define BATCH 4
#define SEQ   4096
#define M_TOT (BATCH*SEQ)      // 16384
#define NCH 64
#define CHL 64

// ---------------- scratch (device globals; 16B aligned) ----------------
__device__ __align__(16) __half g_xh  [(size_t)M_TOT*HID];
__device__ __align__(16) __half g_w1h [(size_t)EXPD*HID];
__device__ __align__(16) __half g_w2h [(size_t)EXPD*HID];
__device__ __align__(16) __half g_wzh [(size_t)EXPD*EXPD];
__device__ __align__(16) __half g_whh [(size_t)EXPD*EXPD];
__device__ __align__(16) __half g_woh [(size_t)HID*EXPD];
__device__ __align__(16) __half g_xin [(size_t)M_TOT*EXPD];
__device__ __align__(16) __half g_z   [(size_t)M_TOT*EXPD];
__device__ __align__(16) __half g_ht  [(size_t)M_TOT*EXPD];
__device__ __align__(16) __half g_xskip[(size_t)M_TOT*EXPD];
__device__ __align__(16) __half g_u   [(size_t)M_TOT*EXPD];
__device__ __align__(16) float g_aggA [(size_t)BATCH*NCH*EXPD];
__device__ __align__(16) float g_aggB [(size_t)BATCH*NCH*EXPD];
__device__ __align__(16) float g_carry[(size_t)BATCH*NCH*EXPD];

// ---------------- PTX helpers (base-target features only) ----------------
__device__ __forceinline__ uint32_t smem_u32(const void* p) {
    uint32_t a;
    asm("{ .reg .u64 t; cvta.to.shared.u64 t, %1; cvt.u32.u64 %0, t; }" : "=r"(a) : "l"(p));
    return a;
}
__device__ __forceinline__ void cp16(uint32_t dst, const void* src) {
    asm volatile("cp.async.cg.shared.global [%0], [%1], 16;" :: "r"(dst), "l"(src));
}
#define CP_COMMIT() asm volatile("cp.async.commit_group;" ::: "memory")
#define CP_WAIT(n)  asm volatile("cp.async.wait_group %0;" :: "n"(n) : "memory")

__device__ __forceinline__ void ldsm4(uint32_t* r, uint32_t addr) {
    asm volatile("ldmatrix.sync.aligned.m8n8.x4.shared.b16 {%0,%1,%2,%3}, [%4];"
        : "=r"(r[0]), "=r"(r[1]), "=r"(r[2]), "=r"(r[3]) : "r"(addr));
}
__device__ __forceinline__ void mma_f16(float* c, const uint32_t* a, const uint32_t* b) {
    asm volatile(
        "mma.sync.aligned.m16n8k16.row.col.f32.f16.f16.f32 "
        "{%0,%1,%2,%3}, {%4,%5,%6,%7}, {%8,%9}, {%0,%1,%2,%3};"
        : "+f"(c[0]), "+f"(c[1]), "+f"(c[2]), "+f"(c[3])
        : "r"(a[0]), "r"(a[1]), "r"(a[2]), "r"(a[3]), "r"(b[0]), "r"(b[1]));
}

// ---------------- mma.sync GEMM: C[M,N] = act(A[M,K] @ (B[N,K])^T + bias) ------
// fp16 x fp16 -> fp32 acc. 256 threads: 8 warps, 4m x 2n, warp tile 32x64.
// 2 CTAs/SM (regs capped at 128, smem 96KB/CTA).
#define BM 128
#define BN 128
#define BK 64
#define NTHREADS 256
#define T_A 0
#define T_B 16384
#define STAGE_BYTES 32768
#define NSTAGE 3
#define SMEM_BYTES (NSTAGE*STAGE_BYTES)

// ACT: 0=none 1=silu 2=sigmoid ; OUT: 0 -> Cf fp32 ; 1 -> Ch fp16
template<int ACT, int OUT>
__global__ __launch_bounds__(NTHREADS, 2)
void gemm_mma(const __half* __restrict__ A, const __half* __restrict__ B,
              const float* __restrict__ bias,
              float* __restrict__ Cf, __half* __restrict__ Ch,
              int M, int N, int K)
{
    extern __shared__ char smem[];
    const uint32_t sb = smem_u32(smem);
    const int tid  = threadIdx.x;
    const int wid  = tid >> 5;
    const int lane = tid & 31;
    const int wm = wid >> 1;           // 0..3  -> m offset wm*32
    const int wn = wid & 1;            // 0..1  -> n offset wn*64
    const int bm = blockIdx.y * BM;
    const int bn = blockIdx.x * BN;

    const int Kv = K >> 3;             // row pitch in uint4 (8 fp16)
    const uint4* gA = (const uint4*)A;
    const uint4* gB = (const uint4*)B;

    const int nk = K / BK;

    auto load_stage = [&](int buf, int kc) {
        const int kv0 = kc * (BK / 8);
        const uint32_t base = sb + buf * STAGE_BYTES;
        #pragma unroll
        for (int t = 0; t < 4; t++) {           // A: 128 rows x 8 chunks
            int i = tid + t * NTHREADS;
            int row = i >> 3, ch = i & 7;
            uint32_t so = (uint32_t)(row * 128 + ((ch ^ (row & 7)) << 4));
            cp16(base + T_A + so, gA + (size_t)(bm + row) * Kv + kv0 + ch);
        }
        #pragma unroll
        for (int t = 0; t < 4; t++) {           // B: 128 rows x 8 chunks
            int i = tid + t * NTHREADS;
            int row = i >> 3, ch = i & 7;
            uint32_t so = (uint32_t)(row * 128 + ((ch ^ (row & 7)) << 4));
            cp16(base + T_B + so, gB + (size_t)(bn + row) * Kv + kv0 + ch);
        }
    };

    float acc[2][8][4];
    #pragma unroll
    for (int mi = 0; mi < 2; mi++)
        #pragma unroll
        for (int ni = 0; ni < 8; ni++)
            #pragma unroll
            for (int q = 0; q < 4; q++)
                acc[mi][ni][q] = 0.f;

    load_stage(0, 0);
    CP_COMMIT();
    load_stage(1, 1);
    CP_COMMIT();

    for (int kc = 0; kc < nk; kc++) {
        const int buf = kc % NSTAGE;
        if (kc + 1 < nk) { CP_WAIT(1); } else { CP_WAIT(0); }
        __syncthreads();
        if (kc + 2 < nk) {
            load_stage((kc + 2) % NSTAGE, kc + 2);
            CP_COMMIT();
        }

        const uint32_t st = sb + buf * STAGE_BYTES;
        #pragma unroll
        for (int kk = 0; kk < BK / 16; kk++) {
            const int byteCol = kk * 32 + ((lane >> 4) << 4);
            uint32_t ah[2][4];
            #pragma unroll
            for (int mi = 0; mi < 2; mi++) {
                int row = wm * 32 + mi * 16 + (lane & 15);
                uint32_t so = (uint32_t)(row * 128 + byteCol) ^ ((uint32_t)(row & 7) << 4);
                ldsm4(ah[mi], st + T_A + so);
            }
            #pragma unroll
            for (int nt = 0; nt < 4; nt++) {
                int row = wn * 64 + nt * 16 + (lane & 15);
                uint32_t so = (uint32_t)(row * 128 + byteCol) ^ ((uint32_t)(row & 7) << 4);
                uint32_t rh[4];
                ldsm4(rh, st + T_B + so);
                uint32_t b0[2] = { rh[0], rh[2] }, b1[2] = { rh[1], rh[3] };
                #pragma unroll
                for (int mi = 0; mi < 2; mi++) {
                    mma_f16(acc[mi][2*nt+0], ah[mi], b0);
                    mma_f16(acc[mi][2*nt+1], ah[mi], b1);
                }
            }
        }
    }

    // ---------------- epilogue: bias + activation + store ----------------
    const int qrow = lane >> 2;        // 0..7
    const int qcol = (lane & 3) * 2;   // 0,2,4,6
    #pragma unroll
    for (int mi = 0; mi < 2; mi++) {
        #pragma unroll
        for (int ni = 0; ni < 8; ni++) {
            const int n0 = bn + wn * 64 + ni * 8 + qcol;
            const float bias0 = bias[n0], bias1 = bias[n0 + 1];
            #pragma unroll
            for (int half_ = 0; half_ < 2; half_++) {
                const int m = bm + wm * 32 + mi * 16 + qrow + half_ * 8;
                float v0 = acc[mi][ni][half_ * 2 + 0] + bias0;
                float v1 = acc[mi][ni][half_ * 2 + 1] + bias1;
                if (ACT == 1) {
                    v0 *= 1.f / (1.f + expf(-v0));
                    v1 *= 1.f / (1.f + expf(-v1));
                } else if (ACT == 2) {
                    v0 = 1.f / (1.f + expf(-v0));
                    v1 = 1.f / (1.f + expf(-v1));
                }
                if (OUT == 1) {
                    __half h0 = __float2half_rn(v0);
                    __half h1 = __float2half_rn(v1);
                    uint32_t hp = (uint32_t)__half_as_ushort(h0) | ((uint32_t)__half_as_ushort(h1) << 16);
                    *(uint32_t*)&Ch[(size_t)m * N + n0] = hp;
                } else {
                    *(float2*)&Cf[(size_t)m * N + n0] = make_float2(v0, v1);
                }
            }
        }
    }
}

// ---------------- weight transpose: W[K,N] fp32 -> T[N,K] fp16 -------------
__global__ __launch_bounds__(256)
void transpose_h(const float* __restrict__ W, __half* __restrict__ T, int K, int N)
{
    __shared__ float t[32][33];
    const int n0 = blockIdx.x * 32, k0 = blockIdx.y * 32;
    const int tx = threadIdx.x & 31, ty0 = threadIdx.x >> 5;
    #pragma unroll
    for (int dy = 0; dy < 32; dy += 8)
        t[ty0 + dy][tx] = W[(size_t)(k0 + ty0 + dy) * N + n0 + tx];
    __syncthreads();
    #pragma unroll
    for (int dy = 0; dy < 32; dy += 8) {
        int ty = ty0 + dy;
        T[(size_t)(n0 + ty) * K + k0 + tx] = __float2half_rn(t[tx][ty]);
    }
}

// ---------------- x convert: fp32 -> fp16 ----------------
__global__ __launch_bounds__(256)
void convert_h(const float* __restrict__ x, __half* __restrict__ h, int n)
{
    int i = blockIdx.x * blockDim.x + threadIdx.x;
    if (i < n) h[i] = __float2half_rn(x[i]);
}

// ---------------- scan (minGRU linear recurrence), 3-pass chunked ----------------
__global__ __launch_bounds__(256)
void scan_pass1(const __half* __restrict__ z, const __half* __restrict__ ht,
                float* __restrict__ aggA, float* __restrict__ aggB)
{
    int t = blockIdx.x * blockDim.x + threadIdx.x;
    int f = t % EXPD, rc = t / EXPD, c = rc % NCH, bb = rc / NCH;
    size_t base = ((size_t)bb * SEQ + (size_t)c * CHL) * EXPD + f;
    float A = 1.f, B = 0.f;
    #pragma unroll 4
    for (int i = 0; i < CHL; i++) {
        size_t idx = base + (size_t)i * EXPD;
        float zi = __half2float(z[idx]), hi = __half2float(ht[idx]);
        float ai = 1.f - zi, bi = zi * hi;
        A = A * ai;
        B = B * ai + bi;
    }
    aggA[t] = A; aggB[t] = B;
}

__global__ __launch_bounds__(256)
void scan_pass2(const float* __restrict__ aggA, const float* __restrict__ aggB,
                float* __restrict__ carry)
{
    int t = blockIdx.x * blockDim.x + threadIdx.x;
    int f = t % EXPD, bb = t / EXPD;
    size_t base = (size_t)bb * NCH * EXPD + f;
    float h = 0.f;
    for (int c = 0; c < NCH; c++) {
        size_t idx = base + (size_t)c * EXPD;
        carry[idx] = h;
        h = aggA[idx] * h + aggB[idx];
    }
}

__global__ __launch_bounds__(256)
void scan_pass3(const __half* __restrict__ z, const __half* __restrict__ ht,
                const float* __restrict__ carry, const __half* __restrict__ xskip,
                __half* __restrict__ u)
{
    int t = blockIdx.x * blockDim.x + threadIdx.x;
    int f = t % EXPD, rc = t / EXPD, c = rc % NCH, bb = rc / NCH;
    size_t base = ((size_t)bb * SEQ + (size_t)c * CHL) * EXPD + f;
    float h = carry[t];
    #pragma unroll 4
    for (int i = 0; i < CHL; i++) {
        size_t idx = base + (size_t)i * EXPD;
        float zi = __half2float(z[idx]), hti = __half2float(ht[idx]);
        h = (1.f - zi) * h + zi * hti;
        u[idx] = __float2half_rn(__half2float(xskip[idx]) + h);
    }
}

// ---------------- launch ----------------
extern "C" void kernel_launch(void* const* d_in, const int* in_sizes, int n_in,
                              void* d_out, int out_size)
{
    const float* x     = (const float*)d_in[0];
    const float* W_in1 = (const float*)d_in[1];
    const float* b_in1 = (const float*)d_in[2];
    const float* W_in2 = (const float*)d_in[3];
    const float* b_in2 = (const float*)d_in[4];
    const float* W_z   = (const float*)d_in[5];
    const float* b_z   = (const float*)d_in[6];
    const float* W_h   = (const float*)d_in[7];
    const float* b_h   = (const float*)d_in[8];
    const float* W_out = (const float*)d_in[9];
    const float* b_out = (const float*)d_in[10];
    float* out = (float*)d_out;

    __half *xh, *w1h, *w2h, *wzh, *whh, *woh, *xin, *zh, *hth, *xskip, *u;
    float *aggA, *aggB, *carry;
    cudaGetSymbolAddress((void**)&xh, g_xh);
    cudaGetSymbolAddress((void**)&w1h, g_w1h);   cudaGetSymbolAddress((void**)&w2h, g_w2h);
    cudaGetSymbolAddress((void**)&wzh, g_wzh);   cudaGetSymbolAddress((void**)&whh, g_whh);
    cudaGetSymbolAddress((void**)&woh, g_woh);
    cudaGetSymbolAddress((void**)&xin, g_xin);
    cudaGetSymbolAddress((void**)&zh, g_z);      cudaGetSymbolAddress((void**)&hth, g_ht);
    cudaGetSymbolAddress((void**)&xskip, g_xskip);
    cudaGetSymbolAddress((void**)&u, g_u);
    cudaGetSymbolAddress((void**)&aggA, g_aggA); cudaGetSymbolAddress((void**)&aggB, g_aggB);
    cudaGetSymbolAddress((void**)&carry, g_carry);

    cudaFuncSetAttribute(gemm_mma<1,1>, cudaFuncAttributeMaxDynamicSharedMemorySize, SMEM_BYTES);
    cudaFuncSetAttribute(gemm_mma<2,1>, cudaFuncAttributeMaxDynamicSharedMemorySize, SMEM_BYTES);
    cudaFuncSetAttribute(gemm_mma<0,1>, cudaFuncAttributeMaxDynamicSharedMemorySize, SMEM_BYTES);
    cudaFuncSetAttribute(gemm_mma<0,0>, cudaFuncAttributeMaxDynamicSharedMemorySize, SMEM_BYTES);

    // 0: convert x -> fp16
    convert_h<<<(M_TOT * HID + 255) / 256, 256>>>(x, xh, M_TOT * HID);
    // 1: W_in1^T
    transpose_h<<<dim3(EXPD/32, HID/32),  256>>>(W_in1, w1h, HID,  EXPD);
    // 2: W_z^T
    transpose_h<<<dim3(EXPD/32, EXPD/32), 256>>>(W_z,   wzh, EXPD, EXPD);
    // 3: x_in = silu(x@W_in1 + b1) -> fp16
    gemm_mma<1,1><<<dim3(EXPD/BN, M_TOT/BM), NTHREADS, SMEM_BYTES>>>(
        xh, w1h, b_in1, nullptr, xin, M_TOT, EXPD, HID);
    // 4: W_h^T
    transpose_h<<<dim3(EXPD/32, EXPD/32), 256>>>(W_h,   whh, EXPD, EXPD);
    // 5: z = sigmoid(x_in@W_z + bz) -> fp16   <-- ncu samples this launch
    gemm_mma<2,1><<<dim3(EXPD/BN, M_TOT/BM), NTHREADS, SMEM_BYTES>>>(
        xin, wzh, b_z, nullptr, zh, M_TOT, EXPD, EXPD);
    // 6: W_in2^T
    transpose_h<<<dim3(EXPD/32, HID/32),  256>>>(W_in2, w2h, HID,  EXPD);
    // 7: x_skip = silu(x@W_in2 + b2) -> fp16
    gemm_mma<1,1><<<dim3(EXPD/BN, M_TOT/BM), NTHREADS, SMEM_BYTES>>>(
        xh, w2h, b_in2, nullptr, xskip, M_TOT, EXPD, HID);
    // 8: ht = x_in@W_h + bh -> fp16
    gemm_mma<0,1><<<dim3(EXPD/BN, M_TOT/BM), NTHREADS, SMEM_BYTES>>>(
        xin, whh, b_h, nullptr, hth, M_TOT, EXPD, EXPD);
    // 9: W_out^T
    transpose_h<<<dim3(HID/32,  EXPD/32), 256>>>(W_out, woh, EXPD, HID);

    // 10-12: minGRU scan; pass3 fuses u = x_skip + h -> fp16
    int p1 = BATCH * NCH * EXPD;
    scan_pass1<<<p1 / 256, 256>>>(zh, hth, aggA, aggB);
    scan_pass2<<<(BATCH * EXPD) / 256, 256>>>(aggA, aggB, carry);
    scan_pass3<<<p1 / 256, 256>>>(zh, hth, carry, xskip, u);

    // 13: out = u @ W_out + b_out -> fp32
    gemm_mma<0,0><<<dim3(HID/BN, M_TOT/BM), NTHREADS, SMEM_BYTES>>>(
        u, woh, b_out, out, nullptr, M_TOT, HID, EXPD);
}